// round 1
// baseline (speedup 1.0000x reference)
#include <cuda_runtime.h>
#include <math.h>

#define S_LEN 2048
#define D_DIM 2048
#define B_SZ  2
#define NH    16
#define NKV   4
#define HD    128
#define NTOK  (B_SZ * S_LEN)   /* 4096 */
#define KVD   (NKV * HD)       /* 512  */
#define EPS_F 1.1920929e-07f

// Scratch (allocation-free rule: __device__ globals)
__device__ float g_Q[(size_t)NTOK * D_DIM];   // 33.5 MB
__device__ float g_K[(size_t)NTOK * KVD];     //  8.4 MB
__device__ float g_V[(size_t)NTOK * KVD];     //  8.4 MB
__device__ float g_AO[(size_t)NTOK * D_DIM];  // 33.5 MB

// ---------------------------------------------------------------------------
// SGEMM: C[M,N] = A[M,K] @ B[N,K]^T + bias[N]
// Both A and B are K-contiguous (row-major [rows, K]).
// BM=BN=128, BK=16, 256 threads, 8x8 micro-tile.
// M % 128 == 0, N % 128 == 0, K % 16 == 0 hold for all our shapes.
// ---------------------------------------------------------------------------
__global__ __launch_bounds__(256) void sgemm_bias(
    const float* __restrict__ A, const float* __restrict__ Bm,
    const float* __restrict__ bias, float* __restrict__ C,
    int M, int N, int K)
{
    __shared__ __align__(16) float As[16][128];
    __shared__ __align__(16) float Bs[16][128];

    const int tid = threadIdx.x;
    const int tx = tid & 15;
    const int ty = tid >> 4;
    const int rowBase = blockIdx.y * 128;
    const int colBase = blockIdx.x * 128;

    const int lr = tid >> 2;          // 0..63
    const int lk = (tid & 3) << 2;    // 0,4,8,12

    const float* Aptr = A + (size_t)rowBase * K;
    const float* Bptr = Bm + (size_t)colBase * K;

    float acc[8][8];
#pragma unroll
    for (int i = 0; i < 8; i++)
#pragma unroll
        for (int j = 0; j < 8; j++) acc[i][j] = 0.0f;

    for (int k0 = 0; k0 < K; k0 += 16) {
#pragma unroll
        for (int rr = 0; rr < 2; rr++) {
            int r = lr + rr * 64;
            float4 a = *(const float4*)(Aptr + (size_t)r * K + k0 + lk);
            As[lk + 0][r] = a.x; As[lk + 1][r] = a.y;
            As[lk + 2][r] = a.z; As[lk + 3][r] = a.w;
            float4 b = *(const float4*)(Bptr + (size_t)r * K + k0 + lk);
            Bs[lk + 0][r] = b.x; Bs[lk + 1][r] = b.y;
            Bs[lk + 2][r] = b.z; Bs[lk + 3][r] = b.w;
        }
        __syncthreads();
#pragma unroll
        for (int kk = 0; kk < 16; kk++) {
            float ra[8], rb[8];
            *(float4*)&ra[0] = *(const float4*)&As[kk][ty * 8];
            *(float4*)&ra[4] = *(const float4*)&As[kk][ty * 8 + 4];
            *(float4*)&rb[0] = *(const float4*)&Bs[kk][tx * 8];
            *(float4*)&rb[4] = *(const float4*)&Bs[kk][tx * 8 + 4];
#pragma unroll
            for (int i = 0; i < 8; i++)
#pragma unroll
                for (int j = 0; j < 8; j++)
                    acc[i][j] = fmaf(ra[i], rb[j], acc[i][j]);
        }
        __syncthreads();
    }

#pragma unroll
    for (int i = 0; i < 8; i++) {
        int r = rowBase + ty * 8 + i;
#pragma unroll
        for (int j = 0; j < 8; j += 4) {
            int c = colBase + tx * 8 + j;
            float4 o;
            o.x = acc[i][j + 0] + bias[c + 0];
            o.y = acc[i][j + 1] + bias[c + 1];
            o.z = acc[i][j + 2] + bias[c + 2];
            o.w = acc[i][j + 3] + bias[c + 3];
            *(float4*)(C + (size_t)r * N + c) = o;
        }
    }
}

// ---------------------------------------------------------------------------
// Fused RMSNorm + RoPE (+ q_gain * HD^-0.5 folded for Q).
// One warp per (token, head). Lane l owns pairs (l, l+64) and (l+32, l+96).
// ---------------------------------------------------------------------------
__global__ __launch_bounds__(256) void rms_rope(
    float* __restrict__ T, int nheads, const float* __restrict__ gain,
    float extrascale)
{
    int gw = (blockIdx.x * blockDim.x + threadIdx.x) >> 5;
    int lane = threadIdx.x & 31;
    int token = gw / nheads;
    int h = gw - token * nheads;
    if (token >= NTOK) return;

    float* p = T + (size_t)token * (nheads * HD) + h * HD;
    float a1 = p[lane];
    float b1 = p[lane + 32];
    float a2 = p[lane + 64];
    float b2 = p[lane + 96];

    float ss = a1 * a1 + b1 * b1 + a2 * a2 + b2 * b2;
#pragma unroll
    for (int off = 16; off; off >>= 1)
        ss += __shfl_xor_sync(0xffffffffu, ss, off);

    float g = rsqrtf(ss * (1.0f / 128.0f) + EPS_F);
    if (gain) g *= gain[h];
    g *= extrascale;

    int pos = token & (S_LEN - 1);  // token = b*S + s
    const double cexp = -0.14391156831212788;  // -ln(10000)/64
    float invfa = (float)exp(cexp * (double)lane);
    float invfb = (float)exp(cexp * (double)(lane + 32));
    float sa, ca, sb, cb;
    sincosf((float)pos * invfa, &sa, &ca);
    sincosf((float)pos * invfb, &sb, &cb);

    p[lane]      = (a1 * ca + a2 * sa) * g;
    p[lane + 64] = (a2 * ca - a1 * sa) * g;
    p[lane + 32] = (b1 * cb + b2 * sb) * g;
    p[lane + 96] = (b2 * cb - b1 * sb) * g;
}

// ---------------------------------------------------------------------------
// Causal flash attention. Grid: (qtile=S/64, B*H). 256 threads (16x16).
// Scale and q_gain already folded into Q. GQA: q head h -> kv head h/4.
// Per thread: 4 query rows (ty*4+i) x 4 key cols for scores,
//             4 query rows x 8 out dims (tx*8+jj) for output.
// ---------------------------------------------------------------------------
__global__ __launch_bounds__(256) void flash_attn()
{
    extern __shared__ __align__(16) float smem[];
    float* Qs = smem;                 // [128][64]  (d-major)
    float* Ks = Qs + 128 * 64;        // [32][64]   (d-chunk-major)
    float* Vs = Ks + 32 * 64;         // [64][128]  (key-major)
    float* Ps = Vs + 64 * 128;        // [64][68]   (key-major, padded)

    const int qt = blockIdx.x;
    const int bh = blockIdx.y;
    const int b = bh >> 4;
    const int h = bh & 15;
    const int kvh = h >> 2;
    const int tid = threadIdx.x;
    const int tx = tid & 15;
    const int ty = tid >> 4;

    const float* Qg = g_Q + ((size_t)b * S_LEN) * D_DIM + h * HD;
    const float* Kg = g_K + ((size_t)b * S_LEN) * KVD + kvh * HD;
    const float* Vg = g_V + ((size_t)b * S_LEN) * KVD + kvh * HD;

    // Load Q tile transposed: Qs[d][m]
#pragma unroll
    for (int it = 0; it < 8; it++) {
        int i = tid + it * 256;
        int m = i >> 5;
        int d = (i & 31) << 2;
        float4 v = *(const float4*)(Qg + (size_t)(qt * 64 + m) * D_DIM + d);
        Qs[(d + 0) * 64 + m] = v.x;
        Qs[(d + 1) * 64 + m] = v.y;
        Qs[(d + 2) * 64 + m] = v.z;
        Qs[(d + 3) * 64 + m] = v.w;
    }

    float m_i[4], l_i[4], acc[4][8];
#pragma unroll
    for (int i = 0; i < 4; i++) {
        m_i[i] = -1e30f;
        l_i[i] = 0.0f;
#pragma unroll
        for (int j = 0; j < 8; j++) acc[i][j] = 0.0f;
    }

    for (int kt = 0; kt <= qt; kt++) {
        float sc[4][4];
#pragma unroll
        for (int i = 0; i < 4; i++)
#pragma unroll
            for (int j = 0; j < 4; j++) sc[i][j] = 0.0f;

        for (int d0 = 0; d0 < 128; d0 += 32) {
            __syncthreads();  // prior readers of Ks done (also covers Qs init)
#pragma unroll
            for (int it = 0; it < 2; it++) {
                int i = tid + it * 256;
                int n = i >> 3;
                int dq = (i & 7) << 2;
                float4 v = *(const float4*)(Kg + (size_t)(kt * 64 + n) * KVD + d0 + dq);
                Ks[(dq + 0) * 64 + n] = v.x;
                Ks[(dq + 1) * 64 + n] = v.y;
                Ks[(dq + 2) * 64 + n] = v.z;
                Ks[(dq + 3) * 64 + n] = v.w;
            }
            __syncthreads();
#pragma unroll
            for (int dd = 0; dd < 32; dd++) {
                float rq[4], rk[4];
                *(float4*)rq = *(const float4*)&Qs[(d0 + dd) * 64 + ty * 4];
                *(float4*)rk = *(const float4*)&Ks[dd * 64 + tx * 4];
#pragma unroll
                for (int i = 0; i < 4; i++)
#pragma unroll
                    for (int j = 0; j < 4; j++)
                        sc[i][j] = fmaf(rq[i], rk[j], sc[i][j]);
            }
        }

        // Online softmax update + stage P into smem (transposed to [n][m])
        const bool diag = (kt == qt);
#pragma unroll
        for (int i = 0; i < 4; i++) {
            int qg = qt * 64 + ty * 4 + i;
            if (diag) {
#pragma unroll
                for (int j = 0; j < 4; j++) {
                    int kg = kt * 64 + tx * 4 + j;
                    if (kg > qg) sc[i][j] = -1e30f;
                }
            }
            float mx = fmaxf(fmaxf(sc[i][0], sc[i][1]), fmaxf(sc[i][2], sc[i][3]));
#pragma unroll
            for (int off = 8; off; off >>= 1)
                mx = fmaxf(mx, __shfl_xor_sync(0xffffffffu, mx, off));
            float nm = fmaxf(m_i[i], mx);
            float corr = __expf(m_i[i] - nm);
            float ps = 0.0f;
#pragma unroll
            for (int j = 0; j < 4; j++) {
                float pv = __expf(sc[i][j] - nm);
                Ps[(tx * 4 + j) * 68 + ty * 4 + i] = pv;
                ps += pv;
            }
#pragma unroll
            for (int off = 8; off; off >>= 1)
                ps += __shfl_xor_sync(0xffffffffu, ps, off);
            l_i[i] = l_i[i] * corr + ps;
            m_i[i] = nm;
#pragma unroll
            for (int jj = 0; jj < 8; jj++) acc[i][jj] *= corr;
        }

        // Load V tile [n][d]
#pragma unroll
        for (int it = 0; it < 8; it++) {
            int i = tid + it * 256;
            int n = i >> 5;
            int d = (i & 31) << 2;
            *(float4*)&Vs[n * 128 + d] =
                *(const float4*)(Vg + (size_t)(kt * 64 + n) * KVD + d);
        }
        __syncthreads();  // Ps + Vs visible

        // out += P @ V
#pragma unroll 4
        for (int n = 0; n < 64; n++) {
            float rp[4], rv[8];
            *(float4*)rp = *(const float4*)&Ps[n * 68 + ty * 4];
            *(float4*)&rv[0] = *(const float4*)&Vs[n * 128 + tx * 8];
            *(float4*)&rv[4] = *(const float4*)&Vs[n * 128 + tx * 8 + 4];
#pragma unroll
            for (int i = 0; i < 4; i++)
#pragma unroll
                for (int jj = 0; jj < 8; jj++)
                    acc[i][jj] = fmaf(rp[i], rv[jj], acc[i][jj]);
        }
        __syncthreads();  // protect Ps/Vs before next tile overwrites
    }

    // Write normalized output to g_AO in (b, s, h, d) layout
    float* Og = g_AO + ((size_t)b * S_LEN) * D_DIM + h * HD;
#pragma unroll
    for (int i = 0; i < 4; i++) {
        float inv = 1.0f / l_i[i];
        int qg = qt * 64 + ty * 4 + i;
        float4 o1, o2;
        o1.x = acc[i][0] * inv; o1.y = acc[i][1] * inv;
        o1.z = acc[i][2] * inv; o1.w = acc[i][3] * inv;
        o2.x = acc[i][4] * inv; o2.y = acc[i][5] * inv;
        o2.z = acc[i][6] * inv; o2.w = acc[i][7] * inv;
        *(float4*)(Og + (size_t)qg * D_DIM + tx * 8) = o1;
        *(float4*)(Og + (size_t)qg * D_DIM + tx * 8 + 4) = o2;
    }
}

// ---------------------------------------------------------------------------
// Launch
// ---------------------------------------------------------------------------
extern "C" void kernel_launch(void* const* d_in, const int* in_sizes, int n_in,
                              void* d_out, int out_size)
{
    const float* x  = (const float*)d_in[0];
    const float* Wq = (const float*)d_in[1];
    const float* bq = (const float*)d_in[2];
    const float* Wk = (const float*)d_in[3];
    const float* bk = (const float*)d_in[4];
    const float* Wv = (const float*)d_in[5];
    const float* bv = (const float*)d_in[6];
    const float* Wo = (const float*)d_in[7];
    const float* bo = (const float*)d_in[8];
    const float* qg = (const float*)d_in[9];
    float* out = (float*)d_out;

    float *Q, *K, *V, *AO;
    cudaGetSymbolAddress((void**)&Q,  g_Q);
    cudaGetSymbolAddress((void**)&K,  g_K);
    cudaGetSymbolAddress((void**)&V,  g_V);
    cudaGetSymbolAddress((void**)&AO, g_AO);

    const int flash_smem = (128 * 64 + 32 * 64 + 64 * 128 + 64 * 68) * 4;  // 91136
    cudaFuncSetAttribute(flash_attn,
                         cudaFuncAttributeMaxDynamicSharedMemorySize, flash_smem);

    // QKV projections
    sgemm_bias<<<dim3(D_DIM / 128, NTOK / 128), 256>>>(x, Wq, bq, Q, NTOK, D_DIM, D_DIM);
    sgemm_bias<<<dim3(KVD  / 128, NTOK / 128), 256>>>(x, Wk, bk, K, NTOK, KVD,  D_DIM);
    sgemm_bias<<<dim3(KVD  / 128, NTOK / 128), 256>>>(x, Wv, bv, V, NTOK, KVD,  D_DIM);

    // RMSNorm + RoPE (+gain*HD^-0.5 for Q)
    rms_rope<<<(NTOK * NH)  / 8, 256>>>(Q, NH,  qg,      0.088388347648318447f);
    rms_rope<<<(NTOK * NKV) / 8, 256>>>(K, NKV, nullptr, 1.0f);

    // Causal flash attention
    flash_attn<<<dim3(S_LEN / 64, B_SZ * NH), 256, flash_smem>>>();

    // Output projection
    sgemm_bias<<<dim3(D_DIM / 128, NTOK / 128), 256>>>(AO, Wo, bo, out, NTOK, D_DIM, D_DIM);
}

// round 3
// speedup vs baseline: 1.4398x; 1.4398x over previous
#include <cuda_runtime.h>
#include <cstdint>
#include <math.h>

#define S_LEN 2048
#define D_DIM 2048
#define B_SZ  2
#define NH    16
#define NKV   4
#define HD    128
#define NTOK  (B_SZ * S_LEN)   /* 4096 */
#define KVD   (NKV * HD)       /* 512  */
#define EPS_F 1.1920929e-07f

// Scratch (allocation-free rule: __device__ globals)
__device__ float g_Q[(size_t)NTOK * D_DIM];   // 33.5 MB
__device__ float g_K[(size_t)NTOK * KVD];     //  8.4 MB
__device__ float g_V[(size_t)NTOK * KVD];     //  8.4 MB
__device__ float g_AO[(size_t)NTOK * D_DIM];  // 33.5 MB

__device__ __forceinline__ uint32_t f2tf32(float x) {
    uint32_t r;
    asm("cvt.rna.tf32.f32 %0, %1;" : "=r"(r) : "f"(x));
    return r;
}

// mma.sync m16n8k8 tf32: D = A(row) * B(col) + C, all f32 accum.
__device__ __forceinline__ void mma_tf32(
    float& c0, float& c1, float& c2, float& c3,
    uint32_t a0, uint32_t a1, uint32_t a2, uint32_t a3,
    uint32_t b0, uint32_t b1)
{
    asm volatile(
        "mma.sync.aligned.m16n8k8.row.col.f32.tf32.tf32.f32 "
        "{%0,%1,%2,%3}, {%4,%5,%6,%7}, {%8,%9}, {%0,%1,%2,%3};"
        : "+f"(c0), "+f"(c1), "+f"(c2), "+f"(c3)
        : "r"(a0), "r"(a1), "r"(a2), "r"(a3), "r"(b0), "r"(b1));
}

// ---------------------------------------------------------------------------
// tf32 tensor-core GEMM: C[M,N] = A[M,K] @ B[N,K]^T + bias[N]
// BM=BN=128, BK=16, 256 threads (8 warps, 4x2), warp tile 32x64.
// Smem K-permuted so each fragment load is one LDS.128 covering both k-steps.
// M%128==0, N%128==0, K%16==0.
// ---------------------------------------------------------------------------
#define SROW 20   // smem row stride in floats (16 + 4 pad; 80B keeps float4 align)

__global__ __launch_bounds__(256) void gemm_tf32mma(
    const float* __restrict__ A, const float* __restrict__ Bm,
    const float* __restrict__ bias, float* __restrict__ C,
    int N, int K)
{
    __shared__ __align__(16) uint32_t sA[2][128 * SROW];
    __shared__ __align__(16) uint32_t sB[2][128 * SROW];

    const int tid = threadIdx.x;
    const int lane = tid & 31, wid = tid >> 5;
    const int wm = wid >> 1, wn = wid & 1;       // 4 x 2 warp grid
    const int g = lane >> 2, tg = lane & 3;      // groupID, threadInGroup
    const int rowBase = blockIdx.y * 128;
    const int colBase = blockIdx.x * 128;
    const float* Ap = A + (size_t)rowBase * K;
    const float* Bp = Bm + (size_t)colBase * K;

    // Loader mapping: thread -> (row, two float4 chunks of the 16-wide k slab)
    const int lrow = tid >> 1;
    const int lc4 = (tid & 1) * 2;   // float4 index base: 0 or 2

    float acc[2][8][4];
#pragma unroll
    for (int mt = 0; mt < 2; mt++)
#pragma unroll
        for (int nt = 0; nt < 8; nt++)
#pragma unroll
            for (int r = 0; r < 4; r++) acc[mt][nt][r] = 0.0f;

    const int NT = K >> 4;

    // Fill buffer 0 (k-permuted: k = 4*c4 + j  ->  pos = j*4 + c4)
    {
#pragma unroll
        for (int i = 0; i < 2; i++) {
            int c4 = lc4 + i;
            float4 av = *(const float4*)(Ap + (size_t)lrow * K + 4 * c4);
            uint32_t* dst = &sA[0][lrow * SROW + c4];
            dst[0] = f2tf32(av.x); dst[4] = f2tf32(av.y);
            dst[8] = f2tf32(av.z); dst[12] = f2tf32(av.w);
            float4 bv = *(const float4*)(Bp + (size_t)lrow * K + 4 * c4);
            uint32_t* dstB = &sB[0][lrow * SROW + c4];
            dstB[0] = f2tf32(bv.x); dstB[4] = f2tf32(bv.y);
            dstB[8] = f2tf32(bv.z); dstB[12] = f2tf32(bv.w);
        }
    }
    __syncthreads();

    for (int t = 0; t < NT; t++) {
        const int cur = t & 1;
        const bool pref = (t + 1 < NT);
        float4 pa[2], pb[2];
        if (pref) {
            const int k0 = (t + 1) << 4;
#pragma unroll
            for (int i = 0; i < 2; i++) {
                pa[i] = *(const float4*)(Ap + (size_t)lrow * K + k0 + 4 * (lc4 + i));
                pb[i] = *(const float4*)(Bp + (size_t)lrow * K + k0 + 4 * (lc4 + i));
            }
        }

        // Fragment loads: one LDS.128 each, covering both k-steps.
        uint4 afr[2][2];  // [mt][row: g, g+8]
#pragma unroll
        for (int mt = 0; mt < 2; mt++) {
            const int r0 = wm * 32 + mt * 16 + g;
            afr[mt][0] = *(const uint4*)&sA[cur][r0 * SROW + 4 * tg];
            afr[mt][1] = *(const uint4*)&sA[cur][(r0 + 8) * SROW + 4 * tg];
        }
        uint4 bfr[8];
#pragma unroll
        for (int nt = 0; nt < 8; nt++) {
            const int rn = wn * 64 + nt * 8 + g;
            bfr[nt] = *(const uint4*)&sB[cur][rn * SROW + 4 * tg];
        }

        // k-step 0: A cols {tg, tg+4} = (.x, .y); B rows {tg, tg+4} = (.x, .y)
#pragma unroll
        for (int mt = 0; mt < 2; mt++)
#pragma unroll
            for (int nt = 0; nt < 8; nt++)
                mma_tf32(acc[mt][nt][0], acc[mt][nt][1], acc[mt][nt][2], acc[mt][nt][3],
                         afr[mt][0].x, afr[mt][1].x, afr[mt][0].y, afr[mt][1].y,
                         bfr[nt].x, bfr[nt].y);
        // k-step 1: (.z, .w)
#pragma unroll
        for (int mt = 0; mt < 2; mt++)
#pragma unroll
            for (int nt = 0; nt < 8; nt++)
                mma_tf32(acc[mt][nt][0], acc[mt][nt][1], acc[mt][nt][2], acc[mt][nt][3],
                         afr[mt][0].z, afr[mt][1].z, afr[mt][0].w, afr[mt][1].w,
                         bfr[nt].z, bfr[nt].w);

        if (pref) {
            const int nxt = cur ^ 1;
#pragma unroll
            for (int i = 0; i < 2; i++) {
                const int c4 = lc4 + i;
                uint32_t* dst = &sA[nxt][lrow * SROW + c4];
                dst[0] = f2tf32(pa[i].x); dst[4] = f2tf32(pa[i].y);
                dst[8] = f2tf32(pa[i].z); dst[12] = f2tf32(pa[i].w);
                uint32_t* dstB = &sB[nxt][lrow * SROW + c4];
                dstB[0] = f2tf32(pb[i].x); dstB[4] = f2tf32(pb[i].y);
                dstB[8] = f2tf32(pb[i].z); dstB[12] = f2tf32(pb[i].w);
            }
        }
        __syncthreads();
    }

    // Epilogue: c0,c1 at (row, col..col+1); c2,c3 at (row+8, ...)
#pragma unroll
    for (int mt = 0; mt < 2; mt++) {
        const int row = rowBase + wm * 32 + mt * 16 + g;
#pragma unroll
        for (int nt = 0; nt < 8; nt++) {
            const int col = colBase + wn * 64 + nt * 8 + 2 * tg;
            const float2 bb = *(const float2*)(bias + col);
            float2 o0, o1;
            o0.x = acc[mt][nt][0] + bb.x;
            o0.y = acc[mt][nt][1] + bb.y;
            o1.x = acc[mt][nt][2] + bb.x;
            o1.y = acc[mt][nt][3] + bb.y;
            *(float2*)(C + (size_t)row * N + col) = o0;
            *(float2*)(C + (size_t)(row + 8) * N + col) = o1;
        }
    }
}

// ---------------------------------------------------------------------------
// Fused RMSNorm + RoPE (+ q_gain * HD^-0.5 folded for Q).
// One warp per (token, head). Lane l owns pairs (l, l+64) and (l+32, l+96).
// ---------------------------------------------------------------------------
__global__ __launch_bounds__(256) void rms_rope(
    float* __restrict__ T, int nheads, const float* __restrict__ gain,
    float extrascale)
{
    int gw = (blockIdx.x * blockDim.x + threadIdx.x) >> 5;
    int lane = threadIdx.x & 31;
    int token = gw / nheads;
    int h = gw - token * nheads;
    if (token >= NTOK) return;

    float* p = T + (size_t)token * (nheads * HD) + h * HD;
    float a1 = p[lane];
    float b1 = p[lane + 32];
    float a2 = p[lane + 64];
    float b2 = p[lane + 96];

    float ss = a1 * a1 + b1 * b1 + a2 * a2 + b2 * b2;
#pragma unroll
    for (int off = 16; off; off >>= 1)
        ss += __shfl_xor_sync(0xffffffffu, ss, off);

    float g = rsqrtf(ss * (1.0f / 128.0f) + EPS_F);
    if (gain) g *= gain[h];
    g *= extrascale;

    int pos = token & (S_LEN - 1);  // token = b*S + s
    // inv_freq = 10000^(-lane/64) = exp2(-lane * log2(10000)/64)
    const float c = -0.20762050593046015f;
    float invfa = exp2f(c * (float)lane);
    float invfb = exp2f(c * (float)(lane + 32));
    float sa, ca, sb, cb;
    sincosf((float)pos * invfa, &sa, &ca);
    sincosf((float)pos * invfb, &sb, &cb);

    p[lane]      = (a1 * ca + a2 * sa) * g;
    p[lane + 64] = (a2 * ca - a1 * sa) * g;
    p[lane + 32] = (b1 * cb + b2 * sb) * g;
    p[lane + 96] = (b2 * cb - b1 * sb) * g;
}

// ---------------------------------------------------------------------------
// Causal flash attention (fp32). Grid: (qtile=S/64, B*H). 256 threads (16x16).
// ---------------------------------------------------------------------------
__global__ __launch_bounds__(256) void flash_attn()
{
    extern __shared__ __align__(16) float fsm[];
    float* Qs = fsm;                  // [128][64]  (d-major)
    float* Ks = Qs + 128 * 64;        // [32][64]   (d-chunk-major)
    float* Vs = Ks + 32 * 64;         // [64][128]  (key-major)
    float* Ps = Vs + 64 * 128;        // [64][68]   (key-major, padded)

    const int qt = blockIdx.x;
    const int bh = blockIdx.y;
    const int b = bh >> 4;
    const int h = bh & 15;
    const int kvh = h >> 2;
    const int tid = threadIdx.x;
    const int tx = tid & 15;
    const int ty = tid >> 4;

    const float* Qg = g_Q + ((size_t)b * S_LEN) * D_DIM + h * HD;
    const float* Kg = g_K + ((size_t)b * S_LEN) * KVD + kvh * HD;
    const float* Vg = g_V + ((size_t)b * S_LEN) * KVD + kvh * HD;

#pragma unroll
    for (int it = 0; it < 8; it++) {
        int i = tid + it * 256;
        int m = i >> 5;
        int d = (i & 31) << 2;
        float4 v = *(const float4*)(Qg + (size_t)(qt * 64 + m) * D_DIM + d);
        Qs[(d + 0) * 64 + m] = v.x;
        Qs[(d + 1) * 64 + m] = v.y;
        Qs[(d + 2) * 64 + m] = v.z;
        Qs[(d + 3) * 64 + m] = v.w;
    }

    float m_i[4], l_i[4], acc[4][8];
#pragma unroll
    for (int i = 0; i < 4; i++) {
        m_i[i] = -1e30f;
        l_i[i] = 0.0f;
#pragma unroll
        for (int j = 0; j < 8; j++) acc[i][j] = 0.0f;
    }

    for (int kt = 0; kt <= qt; kt++) {
        float sc[4][4];
#pragma unroll
        for (int i = 0; i < 4; i++)
#pragma unroll
            for (int j = 0; j < 4; j++) sc[i][j] = 0.0f;

        for (int d0 = 0; d0 < 128; d0 += 32) {
            __syncthreads();
#pragma unroll
            for (int it = 0; it < 2; it++) {
                int i = tid + it * 256;
                int n = i >> 3;
                int dq = (i & 7) << 2;
                float4 v = *(const float4*)(Kg + (size_t)(kt * 64 + n) * KVD + d0 + dq);
                Ks[(dq + 0) * 64 + n] = v.x;
                Ks[(dq + 1) * 64 + n] = v.y;
                Ks[(dq + 2) * 64 + n] = v.z;
                Ks[(dq + 3) * 64 + n] = v.w;
            }
            __syncthreads();
#pragma unroll
            for (int dd = 0; dd < 32; dd++) {
                float rq[4], rk[4];
                *(float4*)rq = *(const float4*)&Qs[(d0 + dd) * 64 + ty * 4];
                *(float4*)rk = *(const float4*)&Ks[dd * 64 + tx * 4];
#pragma unroll
                for (int i = 0; i < 4; i++)
#pragma unroll
                    for (int j = 0; j < 4; j++)
                        sc[i][j] = fmaf(rq[i], rk[j], sc[i][j]);
            }
        }

        const bool diag = (kt == qt);
#pragma unroll
        for (int i = 0; i < 4; i++) {
            int qg = qt * 64 + ty * 4 + i;
            if (diag) {
#pragma unroll
                for (int j = 0; j < 4; j++) {
                    int kg = kt * 64 + tx * 4 + j;
                    if (kg > qg) sc[i][j] = -1e30f;
                }
            }
            float mx = fmaxf(fmaxf(sc[i][0], sc[i][1]), fmaxf(sc[i][2], sc[i][3]));
#pragma unroll
            for (int off = 8; off; off >>= 1)
                mx = fmaxf(mx, __shfl_xor_sync(0xffffffffu, mx, off));
            float nm = fmaxf(m_i[i], mx);
            float corr = __expf(m_i[i] - nm);
            float ps = 0.0f;
#pragma unroll
            for (int j = 0; j < 4; j++) {
                float pv = __expf(sc[i][j] - nm);
                Ps[(tx * 4 + j) * 68 + ty * 4 + i] = pv;
                ps += pv;
            }
#pragma unroll
            for (int off = 8; off; off >>= 1)
                ps += __shfl_xor_sync(0xffffffffu, ps, off);
            l_i[i] = l_i[i] * corr + ps;
            m_i[i] = nm;
#pragma unroll
            for (int jj = 0; jj < 8; jj++) acc[i][jj] *= corr;
        }

#pragma unroll
        for (int it = 0; it < 8; it++) {
            int i = tid + it * 256;
            int n = i >> 5;
            int d = (i & 31) << 2;
            *(float4*)&Vs[n * 128 + d] =
                *(const float4*)(Vg + (size_t)(kt * 64 + n) * KVD + d);
        }
        __syncthreads();

#pragma unroll 4
        for (int n = 0; n < 64; n++) {
            float rp[4], rv[8];
            *(float4*)rp = *(const float4*)&Ps[n * 68 + ty * 4];
            *(float4*)&rv[0] = *(const float4*)&Vs[n * 128 + tx * 8];
            *(float4*)&rv[4] = *(const float4*)&Vs[n * 128 + tx * 8 + 4];
#pragma unroll
            for (int i = 0; i < 4; i++)
#pragma unroll
                for (int jj = 0; jj < 8; jj++)
                    acc[i][jj] = fmaf(rp[i], rv[jj], acc[i][jj]);
        }
        __syncthreads();
    }

    float* Og = g_AO + ((size_t)b * S_LEN) * D_DIM + h * HD;
#pragma unroll
    for (int i = 0; i < 4; i++) {
        float inv = 1.0f / l_i[i];
        int qg = qt * 64 + ty * 4 + i;
        float4 o1, o2;
        o1.x = acc[i][0] * inv; o1.y = acc[i][1] * inv;
        o1.z = acc[i][2] * inv; o1.w = acc[i][3] * inv;
        o2.x = acc[i][4] * inv; o2.y = acc[i][5] * inv;
        o2.z = acc[i][6] * inv; o2.w = acc[i][7] * inv;
        *(float4*)(Og + (size_t)qg * D_DIM + tx * 8) = o1;
        *(float4*)(Og + (size_t)qg * D_DIM + tx * 8 + 4) = o2;
    }
}

// ---------------------------------------------------------------------------
// Launch
// ---------------------------------------------------------------------------
extern "C" void kernel_launch(void* const* d_in, const int* in_sizes, int n_in,
                              void* d_out, int out_size)
{
    const float* x  = (const float*)d_in[0];
    const float* Wq = (const float*)d_in[1];
    const float* bq = (const float*)d_in[2];
    const float* Wk = (const float*)d_in[3];
    const float* bk = (const float*)d_in[4];
    const float* Wv = (const float*)d_in[5];
    const float* bv = (const float*)d_in[6];
    const float* Wo = (const float*)d_in[7];
    const float* bo = (const float*)d_in[8];
    const float* qg = (const float*)d_in[9];
    float* out = (float*)d_out;

    float *Q, *K, *V, *AO;
    cudaGetSymbolAddress((void**)&Q,  g_Q);
    cudaGetSymbolAddress((void**)&K,  g_K);
    cudaGetSymbolAddress((void**)&V,  g_V);
    cudaGetSymbolAddress((void**)&AO, g_AO);

    const int flash_smem = (128 * 64 + 32 * 64 + 64 * 128 + 64 * 68) * 4;  // 91136
    cudaFuncSetAttribute(flash_attn,
                         cudaFuncAttributeMaxDynamicSharedMemorySize, flash_smem);

    // QKV projections (tf32 tensor cores)
    gemm_tf32mma<<<dim3(D_DIM / 128, NTOK / 128), 256>>>(x, Wq, bq, Q, D_DIM, D_DIM);
    gemm_tf32mma<<<dim3(KVD  / 128, NTOK / 128), 256>>>(x, Wk, bk, K, KVD,  D_DIM);
    gemm_tf32mma<<<dim3(KVD  / 128, NTOK / 128), 256>>>(x, Wv, bv, V, KVD,  D_DIM);

    // RMSNorm + RoPE (+gain*HD^-0.5 for Q)
    rms_rope<<<(NTOK * NH)  / 8, 256>>>(Q, NH,  qg,      0.088388347648318447f);
    rms_rope<<<(NTOK * NKV) / 8, 256>>>(K, NKV, nullptr, 1.0f);

    // Causal flash attention (fp32)
    flash_attn<<<dim3(S_LEN / 64, B_SZ * NH), 256, flash_smem>>>();

    // Output projection (tf32 tensor cores)
    gemm_tf32mma<<<dim3(D_DIM / 128, NTOK / 128), 256>>>(AO, Wo, bo, out, D_DIM, D_DIM);
}

// round 4
// speedup vs baseline: 1.9675x; 1.3665x over previous
#include <cuda_runtime.h>
#include <cstdint>
#include <math.h>

#define S_LEN 2048
#define D_DIM 2048
#define B_SZ  2
#define NH    16
#define NKV   4
#define HD    128
#define NTOK  (B_SZ * S_LEN)   /* 4096 */
#define KVD   (NKV * HD)       /* 512  */
#define EPS_F 1.1920929e-07f

// Scratch (allocation-free rule: __device__ globals)
__device__ float g_Q[(size_t)NTOK * D_DIM];   // 33.5 MB
__device__ float g_K[(size_t)NTOK * KVD];     //  8.4 MB
__device__ float g_V[(size_t)NTOK * KVD];     //  8.4 MB
__device__ float g_AO[(size_t)NTOK * D_DIM];  // 33.5 MB

__device__ __forceinline__ uint32_t f2tf32(float x) {
    uint32_t r;
    asm("cvt.rna.tf32.f32 %0, %1;" : "=r"(r) : "f"(x));
    return r;
}

// mma.sync m16n8k8 tf32: D = A(row) * B(col) + C, all f32 accum.
__device__ __forceinline__ void mma_tf32(
    float& c0, float& c1, float& c2, float& c3,
    uint32_t a0, uint32_t a1, uint32_t a2, uint32_t a3,
    uint32_t b0, uint32_t b1)
{
    asm volatile(
        "mma.sync.aligned.m16n8k8.row.col.f32.tf32.tf32.f32 "
        "{%0,%1,%2,%3}, {%4,%5,%6,%7}, {%8,%9}, {%0,%1,%2,%3};"
        : "+f"(c0), "+f"(c1), "+f"(c2), "+f"(c3)
        : "r"(a0), "r"(a1), "r"(a2), "r"(a3), "r"(b0), "r"(b1));
}

// ---------------------------------------------------------------------------
// tf32 tensor-core GEMM: C[M,N] = A[M,K] @ B[N,K]^T + bias[N]
// BM=BN=128, BK=16, 256 threads (8 warps, 4x2), warp tile 32x64.
// ---------------------------------------------------------------------------
#define SROW 20

__global__ __launch_bounds__(256) void gemm_tf32mma(
    const float* __restrict__ A, const float* __restrict__ Bm,
    const float* __restrict__ bias, float* __restrict__ C,
    int N, int K)
{
    __shared__ __align__(16) uint32_t sA[2][128 * SROW];
    __shared__ __align__(16) uint32_t sB[2][128 * SROW];

    const int tid = threadIdx.x;
    const int lane = tid & 31, wid = tid >> 5;
    const int wm = wid >> 1, wn = wid & 1;
    const int g = lane >> 2, tg = lane & 3;
    const int rowBase = blockIdx.y * 128;
    const int colBase = blockIdx.x * 128;
    const float* Ap = A + (size_t)rowBase * K;
    const float* Bp = Bm + (size_t)colBase * K;

    const int lrow = tid >> 1;
    const int lc4 = (tid & 1) * 2;

    float acc[2][8][4];
#pragma unroll
    for (int mt = 0; mt < 2; mt++)
#pragma unroll
        for (int nt = 0; nt < 8; nt++)
#pragma unroll
            for (int r = 0; r < 4; r++) acc[mt][nt][r] = 0.0f;

    const int NT = K >> 4;

    {
#pragma unroll
        for (int i = 0; i < 2; i++) {
            int c4 = lc4 + i;
            float4 av = *(const float4*)(Ap + (size_t)lrow * K + 4 * c4);
            uint32_t* dst = &sA[0][lrow * SROW + c4];
            dst[0] = f2tf32(av.x); dst[4] = f2tf32(av.y);
            dst[8] = f2tf32(av.z); dst[12] = f2tf32(av.w);
            float4 bv = *(const float4*)(Bp + (size_t)lrow * K + 4 * c4);
            uint32_t* dstB = &sB[0][lrow * SROW + c4];
            dstB[0] = f2tf32(bv.x); dstB[4] = f2tf32(bv.y);
            dstB[8] = f2tf32(bv.z); dstB[12] = f2tf32(bv.w);
        }
    }
    __syncthreads();

    for (int t = 0; t < NT; t++) {
        const int cur = t & 1;
        const bool pref = (t + 1 < NT);
        float4 pa[2], pb[2];
        if (pref) {
            const int k0 = (t + 1) << 4;
#pragma unroll
            for (int i = 0; i < 2; i++) {
                pa[i] = *(const float4*)(Ap + (size_t)lrow * K + k0 + 4 * (lc4 + i));
                pb[i] = *(const float4*)(Bp + (size_t)lrow * K + k0 + 4 * (lc4 + i));
            }
        }

        uint4 afr[2][2];
#pragma unroll
        for (int mt = 0; mt < 2; mt++) {
            const int r0 = wm * 32 + mt * 16 + g;
            afr[mt][0] = *(const uint4*)&sA[cur][r0 * SROW + 4 * tg];
            afr[mt][1] = *(const uint4*)&sA[cur][(r0 + 8) * SROW + 4 * tg];
        }
        uint4 bfr[8];
#pragma unroll
        for (int nt = 0; nt < 8; nt++) {
            const int rn = wn * 64 + nt * 8 + g;
            bfr[nt] = *(const uint4*)&sB[cur][rn * SROW + 4 * tg];
        }

#pragma unroll
        for (int mt = 0; mt < 2; mt++)
#pragma unroll
            for (int nt = 0; nt < 8; nt++)
                mma_tf32(acc[mt][nt][0], acc[mt][nt][1], acc[mt][nt][2], acc[mt][nt][3],
                         afr[mt][0].x, afr[mt][1].x, afr[mt][0].y, afr[mt][1].y,
                         bfr[nt].x, bfr[nt].y);
#pragma unroll
        for (int mt = 0; mt < 2; mt++)
#pragma unroll
            for (int nt = 0; nt < 8; nt++)
                mma_tf32(acc[mt][nt][0], acc[mt][nt][1], acc[mt][nt][2], acc[mt][nt][3],
                         afr[mt][0].z, afr[mt][1].z, afr[mt][0].w, afr[mt][1].w,
                         bfr[nt].z, bfr[nt].w);

        if (pref) {
            const int nxt = cur ^ 1;
#pragma unroll
            for (int i = 0; i < 2; i++) {
                const int c4 = lc4 + i;
                uint32_t* dst = &sA[nxt][lrow * SROW + c4];
                dst[0] = f2tf32(pa[i].x); dst[4] = f2tf32(pa[i].y);
                dst[8] = f2tf32(pa[i].z); dst[12] = f2tf32(pa[i].w);
                uint32_t* dstB = &sB[nxt][lrow * SROW + c4];
                dstB[0] = f2tf32(pb[i].x); dstB[4] = f2tf32(pb[i].y);
                dstB[8] = f2tf32(pb[i].z); dstB[12] = f2tf32(pb[i].w);
            }
        }
        __syncthreads();
    }

#pragma unroll
    for (int mt = 0; mt < 2; mt++) {
        const int row = rowBase + wm * 32 + mt * 16 + g;
#pragma unroll
        for (int nt = 0; nt < 8; nt++) {
            const int col = colBase + wn * 64 + nt * 8 + 2 * tg;
            const float2 bb = *(const float2*)(bias + col);
            float2 o0, o1;
            o0.x = acc[mt][nt][0] + bb.x;
            o0.y = acc[mt][nt][1] + bb.y;
            o1.x = acc[mt][nt][2] + bb.x;
            o1.y = acc[mt][nt][3] + bb.y;
            *(float2*)(C + (size_t)row * N + col) = o0;
            *(float2*)(C + (size_t)(row + 8) * N + col) = o1;
        }
    }
}

// ---------------------------------------------------------------------------
// Fused RMSNorm + RoPE (+ q_gain * HD^-0.5 folded for Q).
// ---------------------------------------------------------------------------
__global__ __launch_bounds__(256) void rms_rope(
    float* __restrict__ T, int nheads, const float* __restrict__ gain,
    float extrascale)
{
    int gw = (blockIdx.x * blockDim.x + threadIdx.x) >> 5;
    int lane = threadIdx.x & 31;
    int token = gw / nheads;
    int h = gw - token * nheads;
    if (token >= NTOK) return;

    float* p = T + (size_t)token * (nheads * HD) + h * HD;
    float a1 = p[lane];
    float b1 = p[lane + 32];
    float a2 = p[lane + 64];
    float b2 = p[lane + 96];

    float ss = a1 * a1 + b1 * b1 + a2 * a2 + b2 * b2;
#pragma unroll
    for (int off = 16; off; off >>= 1)
        ss += __shfl_xor_sync(0xffffffffu, ss, off);

    float g = rsqrtf(ss * (1.0f / 128.0f) + EPS_F);
    if (gain) g *= gain[h];
    g *= extrascale;

    int pos = token & (S_LEN - 1);
    const float c = -0.20762050593046015f;  // -log2(10000)/64
    float invfa = exp2f(c * (float)lane);
    float invfb = exp2f(c * (float)(lane + 32));
    float sa, ca, sb, cb;
    sincosf((float)pos * invfa, &sa, &ca);
    sincosf((float)pos * invfb, &sb, &cb);

    p[lane]      = (a1 * ca + a2 * sa) * g;
    p[lane + 64] = (a2 * ca - a1 * sa) * g;
    p[lane + 32] = (b1 * cb + b2 * sb) * g;
    p[lane + 96] = (b2 * cb - b1 * sb) * g;
}

// ---------------------------------------------------------------------------
// Causal flash attention, tf32 tensor cores.
// Q-tile 128, K-tile 64. 256 threads = 8 warps; warp w owns q rows w*16..+15.
// Smem k-permuted tf32 (16-chunk: pos = (k&3)*4 + (k>>2)) -> LDS.128 frags.
// Grid: (S/128, B*H). Scale/gain pre-folded into Q.
// ---------------------------------------------------------------------------
#define QROWS 132   // Qs/Ks row stride (floats): 128 + 4, 16B-aligned
#define VROWS 68    // Vt/Ps row stride: 64 + 4, 16B-aligned

__global__ __launch_bounds__(256) void flash_tf32()
{
    extern __shared__ __align__(16) uint32_t usm[];
    uint32_t* Qs = usm;                    // [128][QROWS]
    uint32_t* Ks = Qs + 128 * QROWS;       // [64][QROWS]
    uint32_t* Vt = Ks + 64 * QROWS;        // [128][VROWS]  (d-major, key inner)
    uint32_t* Ps = Vt + 128 * VROWS;       // [8][16][VROWS] warp-private P

    const int qt = blockIdx.x, bh = blockIdx.y;
    const int b = bh >> 4, h = bh & 15, kvh = h >> 2;
    const int tid = threadIdx.x;
    const int lane = tid & 31, w = tid >> 5;
    const int g = lane >> 2, tg = lane & 3;

    const float* Qg = g_Q + ((size_t)(b * S_LEN + qt * 128)) * D_DIM + h * HD;
    const float* Kg = g_K + ((size_t)b * S_LEN) * KVD + kvh * HD;
    const float* Vg = g_V + ((size_t)b * S_LEN) * KVD + kvh * HD;

    // Load Q tile once (k-permuted tf32)
#pragma unroll
    for (int i = 0; i < 16; i++) {
        int idx = tid + i * 256;
        int row = idx >> 5, c4 = idx & 31;
        float4 v = *(const float4*)(Qg + (size_t)row * D_DIM + c4 * 4);
        uint32_t* dst = &Qs[row * QROWS + (c4 >> 2) * 16 + (c4 & 3)];
        dst[0] = f2tf32(v.x); dst[4] = f2tf32(v.y);
        dst[8] = f2tf32(v.z); dst[12] = f2tf32(v.w);
    }

    float o[16][4];
#pragma unroll
    for (int nt = 0; nt < 16; nt++)
#pragma unroll
        for (int r = 0; r < 4; r++) o[nt][r] = 0.0f;
    float m0 = -1e30f, m1 = -1e30f, l0 = 0.0f, l1 = 0.0f;

    uint32_t* Pw = Ps + w * 16 * VROWS;
    const int nkt = 2 * qt + 2;

    for (int kt = 0; kt < nkt; kt++) {
        __syncthreads();  // prior tile's K/Vt readers done (covers Q init too)
        // K tile: [64 keys][128 hd], k-permuted
#pragma unroll
        for (int i = 0; i < 8; i++) {
            int idx = tid + i * 256;
            int row = idx >> 5, c4 = idx & 31;
            float4 v = *(const float4*)(Kg + (size_t)(kt * 64 + row) * KVD + c4 * 4);
            uint32_t* dst = &Ks[row * QROWS + (c4 >> 2) * 16 + (c4 & 3)];
            dst[0] = f2tf32(v.x); dst[4] = f2tf32(v.y);
            dst[8] = f2tf32(v.z); dst[12] = f2tf32(v.w);
        }
        // V tile transposed: Vt[d][key], key-permuted
#pragma unroll
        for (int i = 0; i < 8; i++) {
            int idx = tid + i * 256;
            int key = idx >> 5, c4 = idx & 31;
            float4 v = *(const float4*)(Vg + (size_t)(kt * 64 + key) * KVD + c4 * 4);
            int kp = (key >> 4) * 16 + (key & 3) * 4 + ((key >> 2) & 3);
            int d = c4 * 4;
            Vt[(d + 0) * VROWS + kp] = f2tf32(v.x);
            Vt[(d + 1) * VROWS + kp] = f2tf32(v.y);
            Vt[(d + 2) * VROWS + kp] = f2tf32(v.z);
            Vt[(d + 3) * VROWS + kp] = f2tf32(v.w);
        }
        __syncthreads();

        // S = Q @ K^T  (16 q rows x 64 keys per warp)
        float sacc[8][4];
#pragma unroll
        for (int nt = 0; nt < 8; nt++)
#pragma unroll
            for (int r = 0; r < 4; r++) sacc[nt][r] = 0.0f;

#pragma unroll
        for (int ch = 0; ch < 8; ch++) {
            uint4 a0 = *(const uint4*)&Qs[(w * 16 + g) * QROWS + ch * 16 + 4 * tg];
            uint4 a1 = *(const uint4*)&Qs[(w * 16 + g + 8) * QROWS + ch * 16 + 4 * tg];
#pragma unroll
            for (int nt = 0; nt < 8; nt++) {
                uint4 bf = *(const uint4*)&Ks[(nt * 8 + g) * QROWS + ch * 16 + 4 * tg];
                mma_tf32(sacc[nt][0], sacc[nt][1], sacc[nt][2], sacc[nt][3],
                         a0.x, a1.x, a0.y, a1.y, bf.x, bf.y);
                mma_tf32(sacc[nt][0], sacc[nt][1], sacc[nt][2], sacc[nt][3],
                         a0.z, a1.z, a0.w, a1.w, bf.z, bf.w);
            }
        }

        // Causal mask (diagonal tiles only)
        if (kt >= 2 * qt) {
            const int q0 = qt * 128 + w * 16 + g;
            const int q1 = q0 + 8;
#pragma unroll
            for (int nt = 0; nt < 8; nt++) {
                int k0 = kt * 64 + nt * 8 + 2 * tg;
                if (k0 > q0)     sacc[nt][0] = -1e30f;
                if (k0 + 1 > q0) sacc[nt][1] = -1e30f;
                if (k0 > q1)     sacc[nt][2] = -1e30f;
                if (k0 + 1 > q1) sacc[nt][3] = -1e30f;
            }
        }

        // Online softmax (rows g and g+8; quad reduce over tg)
        float mx0 = -1e30f, mx1 = -1e30f;
#pragma unroll
        for (int nt = 0; nt < 8; nt++) {
            mx0 = fmaxf(mx0, fmaxf(sacc[nt][0], sacc[nt][1]));
            mx1 = fmaxf(mx1, fmaxf(sacc[nt][2], sacc[nt][3]));
        }
        mx0 = fmaxf(mx0, __shfl_xor_sync(0xffffffffu, mx0, 1));
        mx0 = fmaxf(mx0, __shfl_xor_sync(0xffffffffu, mx0, 2));
        mx1 = fmaxf(mx1, __shfl_xor_sync(0xffffffffu, mx1, 1));
        mx1 = fmaxf(mx1, __shfl_xor_sync(0xffffffffu, mx1, 2));
        const float nm0 = fmaxf(m0, mx0), nm1 = fmaxf(m1, mx1);
        const float cr0 = __expf(m0 - nm0), cr1 = __expf(m1 - nm1);
        m0 = nm0; m1 = nm1;

        float s0 = 0.0f, s1 = 0.0f;
#pragma unroll
        for (int nt = 0; nt < 8; nt++) {
#pragma unroll
            for (int jj = 0; jj < 2; jj++) {
                int kk = nt * 8 + 2 * tg + jj;
                int kp = (kk >> 4) * 16 + (kk & 3) * 4 + ((kk >> 2) & 3);
                float p0 = __expf(sacc[nt][jj] - nm0);
                s0 += p0;
                Pw[g * VROWS + kp] = f2tf32(p0);
                float p1 = __expf(sacc[nt][2 + jj] - nm1);
                s1 += p1;
                Pw[(g + 8) * VROWS + kp] = f2tf32(p1);
            }
        }
        s0 += __shfl_xor_sync(0xffffffffu, s0, 1);
        s0 += __shfl_xor_sync(0xffffffffu, s0, 2);
        s1 += __shfl_xor_sync(0xffffffffu, s1, 1);
        s1 += __shfl_xor_sync(0xffffffffu, s1, 2);
        l0 = l0 * cr0 + s0;
        l1 = l1 * cr1 + s1;

#pragma unroll
        for (int nt = 0; nt < 16; nt++) {
            o[nt][0] *= cr0; o[nt][1] *= cr0;
            o[nt][2] *= cr1; o[nt][3] *= cr1;
        }
        __syncwarp();  // Pw stores visible to warp's fragment loads

        // O += P @ V   (16 rows x 128 d per warp, K=64 keys)
#pragma unroll
        for (int ck = 0; ck < 4; ck++) {
            uint4 p0 = *(const uint4*)&Pw[g * VROWS + ck * 16 + 4 * tg];
            uint4 p1 = *(const uint4*)&Pw[(g + 8) * VROWS + ck * 16 + 4 * tg];
#pragma unroll
            for (int nt = 0; nt < 16; nt++) {
                uint4 bf = *(const uint4*)&Vt[(nt * 8 + g) * VROWS + ck * 16 + 4 * tg];
                mma_tf32(o[nt][0], o[nt][1], o[nt][2], o[nt][3],
                         p0.x, p1.x, p0.y, p1.y, bf.x, bf.y);
                mma_tf32(o[nt][0], o[nt][1], o[nt][2], o[nt][3],
                         p0.z, p1.z, p0.w, p1.w, bf.z, bf.w);
            }
        }
        __syncwarp();  // Pw reads done before next tile's stores
    }

    // Normalize + write (b, s, h, d)
    const float inv0 = 1.0f / l0, inv1 = 1.0f / l1;
    float* Og = g_AO + ((size_t)(b * S_LEN + qt * 128 + w * 16)) * D_DIM + h * HD;
#pragma unroll
    for (int nt = 0; nt < 16; nt++) {
        const int col = nt * 8 + 2 * tg;
        float2 e0, e1;
        e0.x = o[nt][0] * inv0; e0.y = o[nt][1] * inv0;
        e1.x = o[nt][2] * inv1; e1.y = o[nt][3] * inv1;
        *(float2*)(Og + (size_t)g * D_DIM + col) = e0;
        *(float2*)(Og + (size_t)(g + 8) * D_DIM + col) = e1;
    }
}

// ---------------------------------------------------------------------------
// Launch
// ---------------------------------------------------------------------------
extern "C" void kernel_launch(void* const* d_in, const int* in_sizes, int n_in,
                              void* d_out, int out_size)
{
    const float* x  = (const float*)d_in[0];
    const float* Wq = (const float*)d_in[1];
    const float* bq = (const float*)d_in[2];
    const float* Wk = (const float*)d_in[3];
    const float* bk = (const float*)d_in[4];
    const float* Wv = (const float*)d_in[5];
    const float* bv = (const float*)d_in[6];
    const float* Wo = (const float*)d_in[7];
    const float* bo = (const float*)d_in[8];
    const float* qg = (const float*)d_in[9];
    float* out = (float*)d_out;

    float *Q, *K, *V, *AO;
    cudaGetSymbolAddress((void**)&Q,  g_Q);
    cudaGetSymbolAddress((void**)&K,  g_K);
    cudaGetSymbolAddress((void**)&V,  g_V);
    cudaGetSymbolAddress((void**)&AO, g_AO);

    const int flash_smem =
        (128 * QROWS + 64 * QROWS + 128 * VROWS + 8 * 16 * VROWS) * 4;  // 171008
    cudaFuncSetAttribute(flash_tf32,
                         cudaFuncAttributeMaxDynamicSharedMemorySize, flash_smem);

    // QKV projections (tf32 tensor cores)
    gemm_tf32mma<<<dim3(D_DIM / 128, NTOK / 128), 256>>>(x, Wq, bq, Q, D_DIM, D_DIM);
    gemm_tf32mma<<<dim3(KVD  / 128, NTOK / 128), 256>>>(x, Wk, bk, K, KVD,  D_DIM);
    gemm_tf32mma<<<dim3(KVD  / 128, NTOK / 128), 256>>>(x, Wv, bv, V, KVD,  D_DIM);

    // RMSNorm + RoPE (+gain*HD^-0.5 for Q)
    rms_rope<<<(NTOK * NH)  / 8, 256>>>(Q, NH,  qg,      0.088388347648318447f);
    rms_rope<<<(NTOK * NKV) / 8, 256>>>(K, NKV, nullptr, 1.0f);

    // Causal flash attention (tf32 tensor cores)
    flash_tf32<<<dim3(S_LEN / 128, B_SZ * NH), 256, flash_smem>>>();

    // Output projection (tf32 tensor cores)
    gemm_tf32mma<<<dim3(D_DIM / 128, NTOK / 128), 256>>>(AO, Wo, bo, out, D_DIM, D_DIM);
}

// round 5
// speedup vs baseline: 3.1117x; 1.5816x over previous
#include <cuda_runtime.h>
#include <cstdint>
#include <math.h>

#define S_LEN 2048
#define D_DIM 2048
#define B_SZ  2
#define NH    16
#define NKV   4
#define HD    128
#define NTOK  (B_SZ * S_LEN)   /* 4096 */
#define KVD   (NKV * HD)       /* 512  */
#define EPS_F 1.1920929e-07f

// Scratch (allocation-free rule: __device__ globals)
__device__ float g_Q[(size_t)NTOK * D_DIM];    // fp32 -> tf32+perm in place
__device__ float g_K[(size_t)NTOK * KVD];
__device__ float g_Vt[(size_t)KVD * NTOK];     // V transposed [KVD][NTOK], tok-perm
__device__ float g_AO[(size_t)NTOK * D_DIM];   // tf32+perm (written by flash)
// Pre-converted (tf32-rounded, 16-chunk k-permuted) operands
__device__ float g_xt[(size_t)NTOK * D_DIM];
__device__ float g_Wqt[(size_t)D_DIM * D_DIM];
__device__ float g_Wkt[(size_t)KVD * D_DIM];
__device__ float g_Wvt[(size_t)KVD * D_DIM];
__device__ float g_Wot[(size_t)D_DIM * D_DIM];

__device__ __forceinline__ uint32_t f2tf32(float x) {
    uint32_t r;
    asm("cvt.rna.tf32.f32 %0, %1;" : "=r"(r) : "f"(x));
    return r;
}
__device__ __forceinline__ uint32_t smem_u32(const void* p) {
    uint32_t a;
    asm("{ .reg .u64 t; cvta.to.shared.u64 t, %1; cvt.u32.u64 %0, t; }"
        : "=r"(a) : "l"(p));
    return a;
}
// involution: swaps the two 2-bit fields of (c & 15)
__device__ __forceinline__ int perm16(int c) {
    return (c & ~15) | ((c & 3) << 2) | ((c >> 2) & 3);
}

#define CP_ASYNC16(dst, src) \
    asm volatile("cp.async.ca.shared.global [%0], [%1], 16;" :: "r"(dst), "l"(src))
#define CP_COMMIT() asm volatile("cp.async.commit_group;" ::: "memory")
#define CP_WAIT2()  asm volatile("cp.async.wait_group 2;" ::: "memory")

// mma.sync m16n8k8 tf32
__device__ __forceinline__ void mma_tf32(
    float& c0, float& c1, float& c2, float& c3,
    uint32_t a0, uint32_t a1, uint32_t a2, uint32_t a3,
    uint32_t b0, uint32_t b1)
{
    asm volatile(
        "mma.sync.aligned.m16n8k8.row.col.f32.tf32.tf32.f32 "
        "{%0,%1,%2,%3}, {%4,%5,%6,%7}, {%8,%9}, {%0,%1,%2,%3};"
        : "+f"(c0), "+f"(c1), "+f"(c2), "+f"(c3)
        : "r"(a0), "r"(a1), "r"(a2), "r"(a3), "r"(b0), "r"(b1));
}

// ---------------------------------------------------------------------------
// Convert fp32 -> tf32(rna) with 16-chunk k-permutation.
// ---------------------------------------------------------------------------
__global__ __launch_bounds__(256) void convert_tf32_perm(
    const float* __restrict__ in, float* __restrict__ out, int n4)
{
    int i = blockIdx.x * 256 + threadIdx.x;
    if (i >= n4) return;
    float4 v = ((const float4*)in)[i];
    int f0 = i << 2;
    int base = f0 & ~15;
    int j = (f0 >> 2) & 3;
    out[base + 0 + j]  = __uint_as_float(f2tf32(v.x));
    out[base + 4 + j]  = __uint_as_float(f2tf32(v.y));
    out[base + 8 + j]  = __uint_as_float(f2tf32(v.z));
    out[base + 12 + j] = __uint_as_float(f2tf32(v.w));
}

// ---------------------------------------------------------------------------
// GEMM v3: C[M,N] = A[M,K] @ B[N,K]^T + bias[N]
// A, B pre-converted tf32 + k-permuted. 4-stage cp.async, BM=BN=128, BK=16.
// 256 threads, 8 warps (4x2), warp tile 32x64.
// blockIdx.z selects operand set 2 (for fused K/V launch).
// vmode 1: write transposed [N][NTOK] with token-perm, tf32-rounded (V).
// ---------------------------------------------------------------------------
__global__ __launch_bounds__(256) void gemm_v3(
    const float* __restrict__ A,
    const float* __restrict__ Bm, const float* __restrict__ bias,
    float* __restrict__ C, int vmode,
    const float* __restrict__ Bm2, const float* __restrict__ bias2,
    float* __restrict__ C2, int vmode2,
    int N, int K)
{
    if (blockIdx.z) { Bm = Bm2; bias = bias2; C = C2; vmode = vmode2; }

    extern __shared__ __align__(16) float gsm[];
    float* sA = gsm;               // [4][128*16]
    float* sB = gsm + 4 * 2048;    // [4][128*16]
    const uint32_t sAu = smem_u32(sA);
    const uint32_t sBu = smem_u32(sB);

    const int tid = threadIdx.x;
    const int lane = tid & 31, wid = tid >> 5;
    const int wm = wid >> 1, wn = wid & 1;
    const int g = lane >> 2, tg = lane & 3;
    const int rowBase = blockIdx.y * 128;
    const int colBase = blockIdx.x * 128;
    const float* Ap = A + (size_t)rowBase * K;
    const float* Bp = Bm + (size_t)colBase * K;

    const int lrow = tid >> 2;       // rows 0..63 (+64 on second pass)
    const int lc4 = tid & 3;

    float acc[2][8][4];
#pragma unroll
    for (int mt = 0; mt < 2; mt++)
#pragma unroll
        for (int nt = 0; nt < 8; nt++)
#pragma unroll
            for (int r = 0; r < 4; r++) acc[mt][nt][r] = 0.0f;

    const int NT = K >> 4;

    auto issue = [&](int slot, int t) {
#pragma unroll
        for (int p = 0; p < 2; p++) {
            const int row = lrow + p * 64;
            const size_t go = (size_t)row * K + t * 16 + lc4 * 4;
            const uint32_t so = (uint32_t)((slot * 2048 + row * 16 + lc4 * 4) * 4);
            CP_ASYNC16(sAu + so, Ap + go);
            CP_ASYNC16(sBu + so, Bp + go);
        }
    };

#pragma unroll
    for (int s = 0; s < 3; s++) { issue(s, s); CP_COMMIT(); }

    for (int t = 0; t < NT; t++) {
        CP_WAIT2();
        __syncthreads();
        const int tn = t + 3;
        if (tn < NT) issue(tn & 3, tn);
        CP_COMMIT();

        const float* bA = sA + (t & 3) * 2048;
        const float* bB = sB + (t & 3) * 2048;

        uint4 afr[2][2];
#pragma unroll
        for (int mt = 0; mt < 2; mt++) {
            const int r0 = wm * 32 + mt * 16 + g;
            afr[mt][0] = *(const uint4*)&bA[r0 * 16 + 4 * tg];
            afr[mt][1] = *(const uint4*)&bA[(r0 + 8) * 16 + 4 * tg];
        }
        uint4 bfr[8];
#pragma unroll
        for (int nt = 0; nt < 8; nt++)
            bfr[nt] = *(const uint4*)&bB[(wn * 64 + nt * 8 + g) * 16 + 4 * tg];

#pragma unroll
        for (int mt = 0; mt < 2; mt++)
#pragma unroll
            for (int nt = 0; nt < 8; nt++)
                mma_tf32(acc[mt][nt][0], acc[mt][nt][1], acc[mt][nt][2], acc[mt][nt][3],
                         afr[mt][0].x, afr[mt][1].x, afr[mt][0].y, afr[mt][1].y,
                         bfr[nt].x, bfr[nt].y);
#pragma unroll
        for (int mt = 0; mt < 2; mt++)
#pragma unroll
            for (int nt = 0; nt < 8; nt++)
                mma_tf32(acc[mt][nt][0], acc[mt][nt][1], acc[mt][nt][2], acc[mt][nt][3],
                         afr[mt][0].z, afr[mt][1].z, afr[mt][0].w, afr[mt][1].w,
                         bfr[nt].z, bfr[nt].w);
    }

    if (!vmode) {
#pragma unroll
        for (int mt = 0; mt < 2; mt++) {
            const int row = rowBase + wm * 32 + mt * 16 + g;
#pragma unroll
            for (int nt = 0; nt < 8; nt++) {
                const int col = colBase + wn * 64 + nt * 8 + 2 * tg;
                const float2 bb = *(const float2*)(bias + col);
                float2 o0, o1;
                o0.x = acc[mt][nt][0] + bb.x;
                o0.y = acc[mt][nt][1] + bb.y;
                o1.x = acc[mt][nt][2] + bb.x;
                o1.y = acc[mt][nt][3] + bb.y;
                *(float2*)(C + (size_t)row * N + col) = o0;
                *(float2*)(C + (size_t)(row + 8) * N + col) = o1;
            }
        }
    } else {
        // V: C[col][perm16(token)] = tf32(acc + bias), C is [N][NTOK]
#pragma unroll
        for (int mt = 0; mt < 2; mt++) {
            const int r = rowBase + wm * 32 + mt * 16 + g;
            const int rp0 = perm16(r);
            const int rp1 = perm16(r + 8);
#pragma unroll
            for (int nt = 0; nt < 8; nt++) {
                const int col = colBase + wn * 64 + nt * 8 + 2 * tg;
                const float b0 = bias[col], b1 = bias[col + 1];
                C[(size_t)col * NTOK + rp0] =
                    __uint_as_float(f2tf32(acc[mt][nt][0] + b0));
                C[(size_t)(col + 1) * NTOK + rp0] =
                    __uint_as_float(f2tf32(acc[mt][nt][1] + b1));
                C[(size_t)col * NTOK + rp1] =
                    __uint_as_float(f2tf32(acc[mt][nt][2] + b0));
                C[(size_t)(col + 1) * NTOK + rp1] =
                    __uint_as_float(f2tf32(acc[mt][nt][3] + b1));
            }
        }
    }
}

// ---------------------------------------------------------------------------
// Fused RMSNorm + RoPE; writes tf32-rounded, k-permuted output in place.
// One warp per (token, head). Lane l owns cols l, l+32, l+64, l+96.
// ---------------------------------------------------------------------------
__global__ __launch_bounds__(256) void rms_rope(
    float* __restrict__ T, int nheads, const float* __restrict__ gain,
    float extrascale)
{
    int gw = (blockIdx.x * blockDim.x + threadIdx.x) >> 5;
    int lane = threadIdx.x & 31;
    int token = gw / nheads;
    int h = gw - token * nheads;
    if (token >= NTOK) return;

    float* p = T + (size_t)token * (nheads * HD) + h * HD;
    float a1 = p[lane];
    float b1 = p[lane + 32];
    float a2 = p[lane + 64];
    float b2 = p[lane + 96];

    float ss = a1 * a1 + b1 * b1 + a2 * a2 + b2 * b2;
#pragma unroll
    for (int off = 16; off; off >>= 1)
        ss += __shfl_xor_sync(0xffffffffu, ss, off);

    float g = rsqrtf(ss * (1.0f / 128.0f) + EPS_F);
    if (gain) g *= gain[h];
    g *= extrascale;

    int pos = token & (S_LEN - 1);
    const float c = -0.20762050593046015f;  // -log2(10000)/64
    float invfa = exp2f(c * (float)lane);
    float invfb = exp2f(c * (float)(lane + 32));
    float sa, ca, sb, cb;
    sincosf((float)pos * invfa, &sa, &ca);
    sincosf((float)pos * invfb, &sb, &cb);

    // all lanes' loads complete before the shuffle reduction, so in-place
    // permuted writes are safe
    p[perm16(lane)]      = __uint_as_float(f2tf32((a1 * ca + a2 * sa) * g));
    p[perm16(lane + 64)] = __uint_as_float(f2tf32((a2 * ca - a1 * sa) * g));
    p[perm16(lane + 32)] = __uint_as_float(f2tf32((b1 * cb + b2 * sb) * g));
    p[perm16(lane + 96)] = __uint_as_float(f2tf32((b2 * cb - b1 * sb) * g));
}

// ---------------------------------------------------------------------------
// Causal flash attention, tf32 tensor cores. All inputs pre-tf32+permuted.
// Q-tile 128, K-tile 64. 8 warps; warp w owns q rows w*16..+15.
// ---------------------------------------------------------------------------
#define QROWS 132
#define VROWS 68

__global__ __launch_bounds__(256) void flash_tf32()
{
    extern __shared__ __align__(16) uint32_t usm[];
    uint32_t* Qs = usm;                    // [128][QROWS]
    uint32_t* Ks = Qs + 128 * QROWS;       // [64][QROWS]
    uint32_t* Vt = Ks + 64 * QROWS;        // [128][VROWS] (d-major, key inner)
    uint32_t* Ps = Vt + 128 * VROWS;       // [8][16][VROWS] warp-private P

    const int qt = blockIdx.x, bh = blockIdx.y;
    const int b = bh >> 4, h = bh & 15, kvh = h >> 2;
    const int tid = threadIdx.x;
    const int lane = tid & 31, w = tid >> 5;
    const int g = lane >> 2, tg = lane & 3;

    const float* Qg = g_Q + ((size_t)(b * S_LEN + qt * 128)) * D_DIM + h * HD;
    const float* Kg = g_K + ((size_t)b * S_LEN) * KVD + kvh * HD;
    const float* Vg = g_Vt + (size_t)(kvh * HD) * NTOK + b * S_LEN;

    // Q tile: straight copy (already tf32+permuted)
#pragma unroll
    for (int i = 0; i < 16; i++) {
        int idx = tid + i * 256;
        int row = idx >> 5, c4 = idx & 31;
        *(uint4*)&Qs[row * QROWS + c4 * 4] =
            *(const uint4*)(Qg + (size_t)row * D_DIM + c4 * 4);
    }

    float o[16][4];
#pragma unroll
    for (int nt = 0; nt < 16; nt++)
#pragma unroll
        for (int r = 0; r < 4; r++) o[nt][r] = 0.0f;
    float m0 = -1e30f, m1 = -1e30f, l0 = 0.0f, l1 = 0.0f;

    uint32_t* Pw = Ps + w * 16 * VROWS;
    const int nkt = 2 * qt + 2;

    for (int kt = 0; kt < nkt; kt++) {
        __syncthreads();
        // K tile [64][128] copy
#pragma unroll
        for (int i = 0; i < 8; i++) {
            int idx = tid + i * 256;
            int row = idx >> 5, c4 = idx & 31;
            *(uint4*)&Ks[row * QROWS + c4 * 4] =
                *(const uint4*)(Kg + (size_t)(kt * 64 + row) * KVD + c4 * 4);
        }
        // V^T tile [128][64] copy (global already transposed + tok-permuted)
#pragma unroll
        for (int i = 0; i < 8; i++) {
            int idx = tid + i * 256;
            int d = idx >> 4, c4 = idx & 15;
            *(uint4*)&Vt[d * VROWS + c4 * 4] =
                *(const uint4*)(Vg + (size_t)d * NTOK + kt * 64 + c4 * 4);
        }
        __syncthreads();

        // S = Q @ K^T
        float sacc[8][4];
#pragma unroll
        for (int nt = 0; nt < 8; nt++)
#pragma unroll
            for (int r = 0; r < 4; r++) sacc[nt][r] = 0.0f;

#pragma unroll
        for (int ch = 0; ch < 8; ch++) {
            uint4 a0 = *(const uint4*)&Qs[(w * 16 + g) * QROWS + ch * 16 + 4 * tg];
            uint4 a1 = *(const uint4*)&Qs[(w * 16 + g + 8) * QROWS + ch * 16 + 4 * tg];
#pragma unroll
            for (int nt = 0; nt < 8; nt++) {
                uint4 bf = *(const uint4*)&Ks[(nt * 8 + g) * QROWS + ch * 16 + 4 * tg];
                mma_tf32(sacc[nt][0], sacc[nt][1], sacc[nt][2], sacc[nt][3],
                         a0.x, a1.x, a0.y, a1.y, bf.x, bf.y);
                mma_tf32(sacc[nt][0], sacc[nt][1], sacc[nt][2], sacc[nt][3],
                         a0.z, a1.z, a0.w, a1.w, bf.z, bf.w);
            }
        }

        if (kt >= 2 * qt) {
            const int q0 = qt * 128 + w * 16 + g;
            const int q1 = q0 + 8;
#pragma unroll
            for (int nt = 0; nt < 8; nt++) {
                int k0 = kt * 64 + nt * 8 + 2 * tg;
                if (k0 > q0)     sacc[nt][0] = -1e30f;
                if (k0 + 1 > q0) sacc[nt][1] = -1e30f;
                if (k0 > q1)     sacc[nt][2] = -1e30f;
                if (k0 + 1 > q1) sacc[nt][3] = -1e30f;
            }
        }

        float mx0 = -1e30f, mx1 = -1e30f;
#pragma unroll
        for (int nt = 0; nt < 8; nt++) {
            mx0 = fmaxf(mx0, fmaxf(sacc[nt][0], sacc[nt][1]));
            mx1 = fmaxf(mx1, fmaxf(sacc[nt][2], sacc[nt][3]));
        }
        mx0 = fmaxf(mx0, __shfl_xor_sync(0xffffffffu, mx0, 1));
        mx0 = fmaxf(mx0, __shfl_xor_sync(0xffffffffu, mx0, 2));
        mx1 = fmaxf(mx1, __shfl_xor_sync(0xffffffffu, mx1, 1));
        mx1 = fmaxf(mx1, __shfl_xor_sync(0xffffffffu, mx1, 2));
        const float nm0 = fmaxf(m0, mx0), nm1 = fmaxf(m1, mx1);
        const float cr0 = __expf(m0 - nm0), cr1 = __expf(m1 - nm1);
        m0 = nm0; m1 = nm1;

        float s0 = 0.0f, s1 = 0.0f;
#pragma unroll
        for (int nt = 0; nt < 8; nt++) {
#pragma unroll
            for (int jj = 0; jj < 2; jj++) {
                int kk = nt * 8 + 2 * tg + jj;
                int kp = perm16(kk);
                float p0 = __expf(sacc[nt][jj] - nm0);
                s0 += p0;
                Pw[g * VROWS + kp] = f2tf32(p0);
                float p1 = __expf(sacc[nt][2 + jj] - nm1);
                s1 += p1;
                Pw[(g + 8) * VROWS + kp] = f2tf32(p1);
            }
        }
        s0 += __shfl_xor_sync(0xffffffffu, s0, 1);
        s0 += __shfl_xor_sync(0xffffffffu, s0, 2);
        s1 += __shfl_xor_sync(0xffffffffu, s1, 1);
        s1 += __shfl_xor_sync(0xffffffffu, s1, 2);
        l0 = l0 * cr0 + s0;
        l1 = l1 * cr1 + s1;

#pragma unroll
        for (int nt = 0; nt < 16; nt++) {
            o[nt][0] *= cr0; o[nt][1] *= cr0;
            o[nt][2] *= cr1; o[nt][3] *= cr1;
        }
        __syncwarp();

        // O += P @ V
#pragma unroll
        for (int ck = 0; ck < 4; ck++) {
            uint4 p0 = *(const uint4*)&Pw[g * VROWS + ck * 16 + 4 * tg];
            uint4 p1 = *(const uint4*)&Pw[(g + 8) * VROWS + ck * 16 + 4 * tg];
#pragma unroll
            for (int nt = 0; nt < 16; nt++) {
                uint4 bf = *(const uint4*)&Vt[(nt * 8 + g) * VROWS + ck * 16 + 4 * tg];
                mma_tf32(o[nt][0], o[nt][1], o[nt][2], o[nt][3],
                         p0.x, p1.x, p0.y, p1.y, bf.x, bf.y);
                mma_tf32(o[nt][0], o[nt][1], o[nt][2], o[nt][3],
                         p0.z, p1.z, p0.w, p1.w, bf.z, bf.w);
            }
        }
        __syncwarp();
    }

    // Normalize + write tf32-rounded, col-permuted (feeds Wo GEMM directly)
    const float inv0 = 1.0f / l0, inv1 = 1.0f / l1;
    float* Og = g_AO + ((size_t)(b * S_LEN + qt * 128 + w * 16)) * D_DIM + h * HD;
#pragma unroll
    for (int nt = 0; nt < 16; nt++) {
        const int col = nt * 8 + 2 * tg;
        const int pc0 = perm16(col), pc1 = perm16(col + 1);
        Og[(size_t)g * D_DIM + pc0] = __uint_as_float(f2tf32(o[nt][0] * inv0));
        Og[(size_t)g * D_DIM + pc1] = __uint_as_float(f2tf32(o[nt][1] * inv0));
        Og[(size_t)(g + 8) * D_DIM + pc0] = __uint_as_float(f2tf32(o[nt][2] * inv1));
        Og[(size_t)(g + 8) * D_DIM + pc1] = __uint_as_float(f2tf32(o[nt][3] * inv1));
    }
}

// ---------------------------------------------------------------------------
// Launch
// ---------------------------------------------------------------------------
extern "C" void kernel_launch(void* const* d_in, const int* in_sizes, int n_in,
                              void* d_out, int out_size)
{
    const float* x  = (const float*)d_in[0];
    const float* Wq = (const float*)d_in[1];
    const float* bq = (const float*)d_in[2];
    const float* Wk = (const float*)d_in[3];
    const float* bk = (const float*)d_in[4];
    const float* Wv = (const float*)d_in[5];
    const float* bv = (const float*)d_in[6];
    const float* Wo = (const float*)d_in[7];
    const float* bo = (const float*)d_in[8];
    const float* qg = (const float*)d_in[9];
    float* out = (float*)d_out;

    float *Q, *K, *Vt, *AO, *xt, *Wqt, *Wkt, *Wvt, *Wot;
    cudaGetSymbolAddress((void**)&Q,   g_Q);
    cudaGetSymbolAddress((void**)&K,   g_K);
    cudaGetSymbolAddress((void**)&Vt,  g_Vt);
    cudaGetSymbolAddress((void**)&AO,  g_AO);
    cudaGetSymbolAddress((void**)&xt,  g_xt);
    cudaGetSymbolAddress((void**)&Wqt, g_Wqt);
    cudaGetSymbolAddress((void**)&Wkt, g_Wkt);
    cudaGetSymbolAddress((void**)&Wvt, g_Wvt);
    cudaGetSymbolAddress((void**)&Wot, g_Wot);

    const int gemm_smem = 4 * 2048 * 2 * 4;  // 65536
    cudaFuncSetAttribute(gemm_v3,
                         cudaFuncAttributeMaxDynamicSharedMemorySize, gemm_smem);
    const int flash_smem =
        (128 * QROWS + 64 * QROWS + 128 * VROWS + 8 * 16 * VROWS) * 4;  // 171008
    cudaFuncSetAttribute(flash_tf32,
                         cudaFuncAttributeMaxDynamicSharedMemorySize, flash_smem);

    // Pre-convert operands to tf32 + k-permuted layout
    convert_tf32_perm<<<(NTOK * D_DIM / 4 + 255) / 256, 256>>>(x,  xt,  NTOK * D_DIM / 4);
    convert_tf32_perm<<<(D_DIM * D_DIM / 4 + 255) / 256, 256>>>(Wq, Wqt, D_DIM * D_DIM / 4);
    convert_tf32_perm<<<(KVD * D_DIM / 4 + 255) / 256, 256>>>(Wk, Wkt, KVD * D_DIM / 4);
    convert_tf32_perm<<<(KVD * D_DIM / 4 + 255) / 256, 256>>>(Wv, Wvt, KVD * D_DIM / 4);
    convert_tf32_perm<<<(D_DIM * D_DIM / 4 + 255) / 256, 256>>>(Wo, Wot, D_DIM * D_DIM / 4);

    // Q projection
    gemm_v3<<<dim3(D_DIM / 128, NTOK / 128, 1), 256, gemm_smem>>>(
        xt, Wqt, bq, Q, 0, nullptr, nullptr, nullptr, 0, D_DIM, D_DIM);
    // K + V projections fused (z=0: K normal; z=1: V transposed+perm+tf32)
    gemm_v3<<<dim3(KVD / 128, NTOK / 128, 2), 256, gemm_smem>>>(
        xt, Wkt, bk, K, 0, Wvt, bv, Vt, 1, KVD, D_DIM);

    // RMSNorm + RoPE (+gain*HD^-0.5 for Q); writes tf32+permuted
    rms_rope<<<(NTOK * NH)  / 8, 256>>>(Q, NH,  qg,      0.088388347648318447f);
    rms_rope<<<(NTOK * NKV) / 8, 256>>>(K, NKV, nullptr, 1.0f);

    // Causal flash attention
    flash_tf32<<<dim3(S_LEN / 128, B_SZ * NH), 256, flash_smem>>>();

    // Output projection
    gemm_v3<<<dim3(D_DIM / 128, NTOK / 128, 1), 256, gemm_smem>>>(
        AO, Wot, bo, out, 0, nullptr, nullptr, nullptr, 0, D_DIM, D_DIM);
}

// round 7
// speedup vs baseline: 3.2948x; 1.0589x over previous
#include <cuda_runtime.h>
#include <cstdint>
#include <math.h>

#define S_LEN 2048
#define D_DIM 2048
#define B_SZ  2
#define NH    16
#define NKV   4
#define HD    128
#define NTOK  (B_SZ * S_LEN)   /* 4096 */
#define KVD   (NKV * HD)       /* 512  */
#define EPS_F 1.1920929e-07f

// Scratch (allocation-free rule: __device__ globals)
__device__ float g_Q[(size_t)NTOK * D_DIM];    // tf32+perm after rms_rope
__device__ float g_K[(size_t)NTOK * KVD];
__device__ float g_Vt[(size_t)KVD * NTOK];     // V^T [KVD][NTOK], tok-perm
__device__ float g_AO[(size_t)NTOK * D_DIM];   // tf32+perm (written by flash)
// Pre-converted (tf32-rounded, 16-chunk k-permuted) operands
__device__ float g_xt[(size_t)NTOK * D_DIM];
__device__ float g_Wqt[(size_t)D_DIM * D_DIM];
__device__ float g_Wkt[(size_t)KVD * D_DIM];
__device__ float g_Wvt[(size_t)KVD * D_DIM];
__device__ float g_Wot[(size_t)D_DIM * D_DIM];

__device__ __forceinline__ uint32_t f2tf32(float x) {
    uint32_t r;
    asm("cvt.rna.tf32.f32 %0, %1;" : "=r"(r) : "f"(x));
    return r;
}
__device__ __forceinline__ uint32_t smem_u32(const void* p) {
    uint32_t a;
    asm("{ .reg .u64 t; cvta.to.shared.u64 t, %1; cvt.u32.u64 %0, t; }"
        : "=r"(a) : "l"(p));
    return a;
}
__device__ __forceinline__ int perm16(int c) {
    return (c & ~15) | ((c & 3) << 2) | ((c >> 2) & 3);
}

#define CP_ASYNC16(dst, src) \
    asm volatile("cp.async.cg.shared.global [%0], [%1], 16;" :: "r"(dst), "l"(src))
#define CP_COMMIT() asm volatile("cp.async.commit_group;" ::: "memory")
#define CP_WAIT(n)  asm volatile("cp.async.wait_group %0;" :: "n"(n) : "memory")

// mma.sync m16n8k8 tf32
__device__ __forceinline__ void mma_tf32(
    float& c0, float& c1, float& c2, float& c3,
    uint32_t a0, uint32_t a1, uint32_t a2, uint32_t a3,
    uint32_t b0, uint32_t b1)
{
    asm volatile(
        "mma.sync.aligned.m16n8k8.row.col.f32.tf32.tf32.f32 "
        "{%0,%1,%2,%3}, {%4,%5,%6,%7}, {%8,%9}, {%0,%1,%2,%3};"
        : "+f"(c0), "+f"(c1), "+f"(c2), "+f"(c3)
        : "r"(a0), "r"(a1), "r"(a2), "r"(a3), "r"(b0), "r"(b1));
}

// ---------------------------------------------------------------------------
// Segmented convert: fp32 -> tf32(rna) + 16-chunk k-perm, all 5 tensors in one
// launch. Segment sizes are compile-time.
// ---------------------------------------------------------------------------
#define N4_X  (NTOK * D_DIM / 4)       /* 2097152 */
#define N4_WQ (D_DIM * D_DIM / 4)      /* 1048576 */
#define N4_WK (KVD * D_DIM / 4)        /*  262144 */
#define SEG0 (N4_X)
#define SEG1 (SEG0 + N4_WQ)
#define SEG2 (SEG1 + N4_WK)
#define SEG3 (SEG2 + N4_WK)
#define SEG4 (SEG3 + N4_WQ)

__global__ __launch_bounds__(256) void convert_all(
    const float* __restrict__ x,  const float* __restrict__ Wq,
    const float* __restrict__ Wk, const float* __restrict__ Wv,
    const float* __restrict__ Wo)
{
    int i = blockIdx.x * 256 + threadIdx.x;
    if (i >= SEG4) return;
    const float* src;
    float* dst;
    int j;
    if (i < SEG0)      { src = x;  dst = g_xt;  j = i; }
    else if (i < SEG1) { src = Wq; dst = g_Wqt; j = i - SEG0; }
    else if (i < SEG2) { src = Wk; dst = g_Wkt; j = i - SEG1; }
    else if (i < SEG3) { src = Wv; dst = g_Wvt; j = i - SEG2; }
    else               { src = Wo; dst = g_Wot; j = i - SEG3; }
    float4 v = ((const float4*)src)[j];
    int f0 = j << 2;
    int base = f0 & ~15;
    int q = (f0 >> 2) & 3;
    dst[base + 0 + q]  = __uint_as_float(f2tf32(v.x));
    dst[base + 4 + q]  = __uint_as_float(f2tf32(v.y));
    dst[base + 8 + q]  = __uint_as_float(f2tf32(v.z));
    dst[base + 12 + q] = __uint_as_float(f2tf32(v.w));
}

// ---------------------------------------------------------------------------
// GEMM v3: C[M,N] = A[M,K] @ B[N,K]^T + bias[N]
// A, B pre-converted tf32 + k-permuted. 4-stage cp.async, BM=BN=128, BK=16.
// vmode 1: write V transposed [N][NTOK] with token-perm, tf32-rounded.
// ---------------------------------------------------------------------------
__global__ __launch_bounds__(256) void gemm_v3(
    const float* __restrict__ A,
    const float* __restrict__ Bm, const float* __restrict__ bias,
    float* __restrict__ C, int vmode,
    const float* __restrict__ BmB, const float* __restrict__ biasB,
    float* __restrict__ CB, int vmodeB,
    int N, int K)
{
    if (blockIdx.z) { Bm = BmB; bias = biasB; C = CB; vmode = vmodeB; }

    extern __shared__ __align__(16) float gsm[];
    float* sA = gsm;               // [4][128*16]
    float* sB = gsm + 4 * 2048;
    const uint32_t sAu = smem_u32(sA);
    const uint32_t sBu = smem_u32(sB);

    const int tid = threadIdx.x;
    const int lane = tid & 31, wid = tid >> 5;
    const int wm = wid >> 1, wn = wid & 1;
    const int g = lane >> 2, tg = lane & 3;
    const int rowBase = blockIdx.y * 128;
    const int colBase = blockIdx.x * 128;
    const float* Ap = A + (size_t)rowBase * K;
    const float* Bp = Bm + (size_t)colBase * K;

    const int lrow = tid >> 2;
    const int lc4 = tid & 3;

    float acc[2][8][4];
#pragma unroll
    for (int mt = 0; mt < 2; mt++)
#pragma unroll
        for (int nt = 0; nt < 8; nt++)
#pragma unroll
            for (int r = 0; r < 4; r++) acc[mt][nt][r] = 0.0f;

    const int NT = K >> 4;

    auto issue = [&](int slot, int t) {
#pragma unroll
        for (int p = 0; p < 2; p++) {
            const int row = lrow + p * 64;
            const size_t go = (size_t)row * K + t * 16 + lc4 * 4;
            const uint32_t so = (uint32_t)((slot * 2048 + row * 16 + lc4 * 4) * 4);
            CP_ASYNC16(sAu + so, Ap + go);
            CP_ASYNC16(sBu + so, Bp + go);
        }
    };

#pragma unroll
    for (int s = 0; s < 3; s++) { issue(s, s); CP_COMMIT(); }

    for (int t = 0; t < NT; t++) {
        CP_WAIT(2);
        __syncthreads();
        const int tn = t + 3;
        if (tn < NT) issue(tn & 3, tn);
        CP_COMMIT();

        const float* bA = sA + (t & 3) * 2048;
        const float* bB = sB + (t & 3) * 2048;

        uint4 afr[2][2];
#pragma unroll
        for (int mt = 0; mt < 2; mt++) {
            const int r0 = wm * 32 + mt * 16 + g;
            afr[mt][0] = *(const uint4*)&bA[r0 * 16 + 4 * tg];
            afr[mt][1] = *(const uint4*)&bA[(r0 + 8) * 16 + 4 * tg];
        }
        uint4 bfr[8];
#pragma unroll
        for (int nt = 0; nt < 8; nt++)
            bfr[nt] = *(const uint4*)&bB[(wn * 64 + nt * 8 + g) * 16 + 4 * tg];

#pragma unroll
        for (int mt = 0; mt < 2; mt++)
#pragma unroll
            for (int nt = 0; nt < 8; nt++)
                mma_tf32(acc[mt][nt][0], acc[mt][nt][1], acc[mt][nt][2], acc[mt][nt][3],
                         afr[mt][0].x, afr[mt][1].x, afr[mt][0].y, afr[mt][1].y,
                         bfr[nt].x, bfr[nt].y);
#pragma unroll
        for (int mt = 0; mt < 2; mt++)
#pragma unroll
            for (int nt = 0; nt < 8; nt++)
                mma_tf32(acc[mt][nt][0], acc[mt][nt][1], acc[mt][nt][2], acc[mt][nt][3],
                         afr[mt][0].z, afr[mt][1].z, afr[mt][0].w, afr[mt][1].w,
                         bfr[nt].z, bfr[nt].w);
    }

    if (!vmode) {
#pragma unroll
        for (int mt = 0; mt < 2; mt++) {
            const int row = rowBase + wm * 32 + mt * 16 + g;
#pragma unroll
            for (int nt = 0; nt < 8; nt++) {
                const int col = colBase + wn * 64 + nt * 8 + 2 * tg;
                const float2 bb = *(const float2*)(bias + col);
                float2 o0, o1;
                o0.x = acc[mt][nt][0] + bb.x;
                o0.y = acc[mt][nt][1] + bb.y;
                o1.x = acc[mt][nt][2] + bb.x;
                o1.y = acc[mt][nt][3] + bb.y;
                *(float2*)(C + (size_t)row * N + col) = o0;
                *(float2*)(C + (size_t)(row + 8) * N + col) = o1;
            }
        }
    } else {
#pragma unroll
        for (int mt = 0; mt < 2; mt++) {
            const int r = rowBase + wm * 32 + mt * 16 + g;
            const int rp0 = perm16(r);
            const int rp1 = perm16(r + 8);
#pragma unroll
            for (int nt = 0; nt < 8; nt++) {
                const int col = colBase + wn * 64 + nt * 8 + 2 * tg;
                const float b0 = bias[col], b1 = bias[col + 1];
                C[(size_t)col * NTOK + rp0] =
                    __uint_as_float(f2tf32(acc[mt][nt][0] + b0));
                C[(size_t)(col + 1) * NTOK + rp0] =
                    __uint_as_float(f2tf32(acc[mt][nt][1] + b1));
                C[(size_t)col * NTOK + rp1] =
                    __uint_as_float(f2tf32(acc[mt][nt][2] + b0));
                C[(size_t)(col + 1) * NTOK + rp1] =
                    __uint_as_float(f2tf32(acc[mt][nt][3] + b1));
            }
        }
    }
}

// ---------------------------------------------------------------------------
// Fused RMSNorm + RoPE; writes tf32-rounded, k-permuted output in place.
// ---------------------------------------------------------------------------
__global__ __launch_bounds__(256) void rms_rope(
    float* __restrict__ T, int nheads, const float* __restrict__ gain,
    float extrascale)
{
    int gw = (blockIdx.x * blockDim.x + threadIdx.x) >> 5;
    int lane = threadIdx.x & 31;
    int token = gw / nheads;
    int h = gw - token * nheads;
    if (token >= NTOK) return;

    float* p = T + (size_t)token * (nheads * HD) + h * HD;
    float a1 = p[lane];
    float b1 = p[lane + 32];
    float a2 = p[lane + 64];
    float b2 = p[lane + 96];

    float ss = a1 * a1 + b1 * b1 + a2 * a2 + b2 * b2;
#pragma unroll
    for (int off = 16; off; off >>= 1)
        ss += __shfl_xor_sync(0xffffffffu, ss, off);

    float g = rsqrtf(ss * (1.0f / 128.0f) + EPS_F);
    if (gain) g *= gain[h];
    g *= extrascale;

    int pos = token & (S_LEN - 1);
    const float c = -0.20762050593046015f;  // -log2(10000)/64
    float invfa = exp2f(c * (float)lane);
    float invfb = exp2f(c * (float)(lane + 32));
    float sa, ca, sb, cb;
    sincosf((float)pos * invfa, &sa, &ca);
    sincosf((float)pos * invfb, &sb, &cb);

    p[perm16(lane)]      = __uint_as_float(f2tf32((a1 * ca + a2 * sa) * g));
    p[perm16(lane + 64)] = __uint_as_float(f2tf32((a2 * ca - a1 * sa) * g));
    p[perm16(lane + 32)] = __uint_as_float(f2tf32((b1 * cb + b2 * sb) * g));
    p[perm16(lane + 96)] = __uint_as_float(f2tf32((b2 * cb - b1 * sb) * g));
}

// ---------------------------------------------------------------------------
// Causal flash attention, tf32 mma + cp.async pipeline.
// Vt[kt] load overlaps S=QK^T; Ks[kt+1] load overlaps softmax+PV.
// Q-tile 128, K-tile 64. 8 warps; warp w owns q rows w*16..+15.
// ---------------------------------------------------------------------------
#define QROWS 132
#define VROWS 68

__global__ __launch_bounds__(256) void flash_tf32()
{
    extern __shared__ __align__(16) uint32_t usm[];
    uint32_t* Qs = usm;                    // [128][QROWS]
    uint32_t* Ks = Qs + 128 * QROWS;       // [64][QROWS]
    uint32_t* Vt = Ks + 64 * QROWS;        // [128][VROWS]
    uint32_t* Ps = Vt + 128 * VROWS;       // [8][16][VROWS] warp-private P
    const uint32_t Ksu = smem_u32(Ks);
    const uint32_t Vtu = smem_u32(Vt);

    const int qt = blockIdx.x, bh = blockIdx.y;
    const int b = bh >> 4, h = bh & 15, kvh = h >> 2;
    const int tid = threadIdx.x;
    const int lane = tid & 31, w = tid >> 5;
    const int g = lane >> 2, tg = lane & 3;

    const float* Qg = g_Q + ((size_t)(b * S_LEN + qt * 128)) * D_DIM + h * HD;
    const float* Kg = g_K + ((size_t)b * S_LEN) * KVD + kvh * HD;
    const float* Vg = g_Vt + (size_t)(kvh * HD) * NTOK + b * S_LEN;

    // cp.async issue helpers (16B each, 8 per thread per tile)
    const int krow = tid >> 5, kc4 = tid & 31;      // K: [64][128]
    const int vd = tid >> 4, vc4 = tid & 15;        // Vt: [128][64]
    auto issueK = [&](int kt) {
#pragma unroll
        for (int i = 0; i < 8; i++) {
            int row = krow + i * 8;
            CP_ASYNC16(Ksu + (uint32_t)((row * QROWS + kc4 * 4) * 4),
                       Kg + (size_t)(kt * 64 + row) * KVD + kc4 * 4);
        }
    };
    auto issueV = [&](int kt) {
#pragma unroll
        for (int i = 0; i < 8; i++) {
            int d = vd + i * 16;
            CP_ASYNC16(Vtu + (uint32_t)((d * VROWS + vc4 * 4) * 4),
                       Vg + (size_t)d * NTOK + kt * 64 + vc4 * 4);
        }
    };

    const int nkt = 2 * qt + 2;
    issueK(0); CP_COMMIT();
    issueV(0); CP_COMMIT();

    // Q tile copy (already tf32+permuted)
#pragma unroll
    for (int i = 0; i < 16; i++) {
        int idx = tid + i * 256;
        int row = idx >> 5, c4 = idx & 31;
        *(uint4*)&Qs[row * QROWS + c4 * 4] =
            *(const uint4*)(Qg + (size_t)row * D_DIM + c4 * 4);
    }

    float o[16][4];
#pragma unroll
    for (int nt = 0; nt < 16; nt++)
#pragma unroll
        for (int r = 0; r < 4; r++) o[nt][r] = 0.0f;
    float m0 = -1e30f, m1 = -1e30f, l0 = 0.0f, l1 = 0.0f;

    uint32_t* Pw = Ps + w * 16 * VROWS;

    for (int kt = 0; kt < nkt; kt++) {
        const int kn = (kt + 1 < nkt) ? kt + 1 : kt;

        CP_WAIT(1);        // Ks[kt] complete (Vt[kt] may be in flight)
        __syncthreads();

        // S = Q @ K^T (overlaps Vt[kt] cp.async)
        float sacc[8][4];
#pragma unroll
        for (int nt = 0; nt < 8; nt++)
#pragma unroll
            for (int r = 0; r < 4; r++) sacc[nt][r] = 0.0f;

#pragma unroll
        for (int ch = 0; ch < 8; ch++) {
            uint4 a0 = *(const uint4*)&Qs[(w * 16 + g) * QROWS + ch * 16 + 4 * tg];
            uint4 a1 = *(const uint4*)&Qs[(w * 16 + g + 8) * QROWS + ch * 16 + 4 * tg];
#pragma unroll
            for (int nt = 0; nt < 8; nt++) {
                uint4 bf = *(const uint4*)&Ks[(nt * 8 + g) * QROWS + ch * 16 + 4 * tg];
                mma_tf32(sacc[nt][0], sacc[nt][1], sacc[nt][2], sacc[nt][3],
                         a0.x, a1.x, a0.y, a1.y, bf.x, bf.y);
                mma_tf32(sacc[nt][0], sacc[nt][1], sacc[nt][2], sacc[nt][3],
                         a0.z, a1.z, a0.w, a1.w, bf.z, bf.w);
            }
        }

        CP_WAIT(0);        // Vt[kt] complete
        __syncthreads();   // all warps done reading Ks[kt]; Vt visible

        issueK(kn); CP_COMMIT();   // overlaps softmax + PV

        if (kt >= 2 * qt) {
            const int q0 = qt * 128 + w * 16 + g;
            const int q1 = q0 + 8;
#pragma unroll
            for (int nt = 0; nt < 8; nt++) {
                int k0 = kt * 64 + nt * 8 + 2 * tg;
                if (k0 > q0)     sacc[nt][0] = -1e30f;
                if (k0 + 1 > q0) sacc[nt][1] = -1e30f;
                if (k0 > q1)     sacc[nt][2] = -1e30f;
                if (k0 + 1 > q1) sacc[nt][3] = -1e30f;
            }
        }

        float mx0 = -1e30f, mx1 = -1e30f;
#pragma unroll
        for (int nt = 0; nt < 8; nt++) {
            mx0 = fmaxf(mx0, fmaxf(sacc[nt][0], sacc[nt][1]));
            mx1 = fmaxf(mx1, fmaxf(sacc[nt][2], sacc[nt][3]));
        }
        mx0 = fmaxf(mx0, __shfl_xor_sync(0xffffffffu, mx0, 1));
        mx0 = fmaxf(mx0, __shfl_xor_sync(0xffffffffu, mx0, 2));
        mx1 = fmaxf(mx1, __shfl_xor_sync(0xffffffffu, mx1, 1));
        mx1 = fmaxf(mx1, __shfl_xor_sync(0xffffffffu, mx1, 2));
        const float nm0 = fmaxf(m0, mx0), nm1 = fmaxf(m1, mx1);
        const float cr0 = __expf(m0 - nm0), cr1 = __expf(m1 - nm1);
        m0 = nm0; m1 = nm1;

        float s0 = 0.0f, s1 = 0.0f;
#pragma unroll
        for (int nt = 0; nt < 8; nt++) {
#pragma unroll
            for (int jj = 0; jj < 2; jj++) {
                int kk = nt * 8 + 2 * tg + jj;
                int kp = perm16(kk);
                float p0 = __expf(sacc[nt][jj] - nm0);
                s0 += p0;
                Pw[g * VROWS + kp] = f2tf32(p0);
                float p1 = __expf(sacc[nt][2 + jj] - nm1);
                s1 += p1;
                Pw[(g + 8) * VROWS + kp] = f2tf32(p1);
            }
        }
        s0 += __shfl_xor_sync(0xffffffffu, s0, 1);
        s0 += __shfl_xor_sync(0xffffffffu, s0, 2);
        s1 += __shfl_xor_sync(0xffffffffu, s1, 1);
        s1 += __shfl_xor_sync(0xffffffffu, s1, 2);
        l0 = l0 * cr0 + s0;
        l1 = l1 * cr1 + s1;

#pragma unroll
        for (int nt = 0; nt < 16; nt++) {
            o[nt][0] *= cr0; o[nt][1] *= cr0;
            o[nt][2] *= cr1; o[nt][3] *= cr1;
        }
        __syncwarp();

        // O += P @ V
#pragma unroll
        for (int ck = 0; ck < 4; ck++) {
            uint4 p0 = *(const uint4*)&Pw[g * VROWS + ck * 16 + 4 * tg];
            uint4 p1 = *(const uint4*)&Pw[(g + 8) * VROWS + ck * 16 + 4 * tg];
#pragma unroll
            for (int nt = 0; nt < 16; nt++) {
                uint4 bf = *(const uint4*)&Vt[(nt * 8 + g) * VROWS + ck * 16 + 4 * tg];
                mma_tf32(o[nt][0], o[nt][1], o[nt][2], o[nt][3],
                         p0.x, p1.x, p0.y, p1.y, bf.x, bf.y);
                mma_tf32(o[nt][0], o[nt][1], o[nt][2], o[nt][3],
                         p0.z, p1.z, p0.w, p1.w, bf.z, bf.w);
            }
        }

        __syncthreads();           // all Vt reads done
        issueV(kn); CP_COMMIT();   // overlaps epilogue / next top
    }

    const float inv0 = 1.0f / l0, inv1 = 1.0f / l1;
    float* Og = g_AO + ((size_t)(b * S_LEN + qt * 128 + w * 16)) * D_DIM + h * HD;
#pragma unroll
    for (int nt = 0; nt < 16; nt++) {
        const int col = nt * 8 + 2 * tg;
        const int pc0 = perm16(col), pc1 = perm16(col + 1);
        Og[(size_t)g * D_DIM + pc0] = __uint_as_float(f2tf32(o[nt][0] * inv0));
        Og[(size_t)g * D_DIM + pc1] = __uint_as_float(f2tf32(o[nt][1] * inv0));
        Og[(size_t)(g + 8) * D_DIM + pc0] = __uint_as_float(f2tf32(o[nt][2] * inv1));
        Og[(size_t)(g + 8) * D_DIM + pc1] = __uint_as_float(f2tf32(o[nt][3] * inv1));
    }
}

// ---------------------------------------------------------------------------
// Launch
// ---------------------------------------------------------------------------
extern "C" void kernel_launch(void* const* d_in, const int* in_sizes, int n_in,
                              void* d_out, int out_size)
{
    const float* x  = (const float*)d_in[0];
    const float* Wq = (const float*)d_in[1];
    const float* bq = (const float*)d_in[2];
    const float* Wk = (const float*)d_in[3];
    const float* bk = (const float*)d_in[4];
    const float* Wv = (const float*)d_in[5];
    const float* bv = (const float*)d_in[6];
    const float* Wo = (const float*)d_in[7];
    const float* bo = (const float*)d_in[8];
    const float* qg = (const float*)d_in[9];
    float* out = (float*)d_out;

    float *Q, *K, *Vt, *AO, *xt, *Wqt, *Wkt, *Wvt, *Wot;
    cudaGetSymbolAddress((void**)&Q,   g_Q);
    cudaGetSymbolAddress((void**)&K,   g_K);
    cudaGetSymbolAddress((void**)&Vt,  g_Vt);
    cudaGetSymbolAddress((void**)&AO,  g_AO);
    cudaGetSymbolAddress((void**)&xt,  g_xt);
    cudaGetSymbolAddress((void**)&Wqt, g_Wqt);
    cudaGetSymbolAddress((void**)&Wkt, g_Wkt);
    cudaGetSymbolAddress((void**)&Wvt, g_Wvt);
    cudaGetSymbolAddress((void**)&Wot, g_Wot);

    const int gemm_smem = 4 * 2048 * 2 * 4;  // 65536
    cudaFuncSetAttribute(gemm_v3,
                         cudaFuncAttributeMaxDynamicSharedMemorySize, gemm_smem);
    const int flash_smem =
        (128 * QROWS + 64 * QROWS + 128 * VROWS + 8 * 16 * VROWS) * 4;  // 171008
    cudaFuncSetAttribute(flash_tf32,
                         cudaFuncAttributeMaxDynamicSharedMemorySize, flash_smem);

    // Pre-convert all operands (single launch)
    convert_all<<<(SEG4 + 255) / 256, 256>>>(x, Wq, Wk, Wv, Wo);

    // Q projection
    gemm_v3<<<dim3(D_DIM / 128, NTOK / 128, 1), 256, gemm_smem>>>(
        xt, Wqt, bq, Q, 0, nullptr, nullptr, nullptr, 0, D_DIM, D_DIM);
    // K + V projections fused (z=1: V transposed+perm+tf32)
    gemm_v3<<<dim3(KVD / 128, NTOK / 128, 2), 256, gemm_smem>>>(
        xt, Wkt, bk, K, 0, Wvt, bv, Vt, 1, KVD, D_DIM);

    // RMSNorm + RoPE (+gain*HD^-0.5 for Q); writes tf32+permuted
    rms_rope<<<(NTOK * NH)  / 8, 256>>>(Q, NH,  qg,      0.088388347648318447f);
    rms_rope<<<(NTOK * NKV) / 8, 256>>>(K, NKV, nullptr, 1.0f);

    // Causal flash attention (pipelined)
    flash_tf32<<<dim3(S_LEN / 128, B_SZ * NH), 256, flash_smem>>>();

    // Output projection
    gemm_v3<<<dim3(D_DIM / 128, NTOK / 128, 1), 256, gemm_smem>>>(
        AO, Wot, bo, out, 0, nullptr, nullptr, nullptr, 0, D_DIM, D_DIM);
}

// round 8
// speedup vs baseline: 3.3513x; 1.0171x over previous
#include <cuda_runtime.h>
#include <cstdint>
#include <math.h>

#define S_LEN 2048
#define D_DIM 2048
#define B_SZ  2
#define NH    16
#define NKV   4
#define HD    128
#define NTOK  (B_SZ * S_LEN)   /* 4096 */
#define KVD   (NKV * HD)       /* 512  */
#define EPS_F 1.1920929e-07f

// Scratch (allocation-free rule: __device__ globals)
__device__ float g_Q[(size_t)NTOK * D_DIM];    // tf32+perm after rms_rope
__device__ float g_K[(size_t)NTOK * KVD];
__device__ float g_Vt[(size_t)KVD * NTOK];     // V^T [KVD][NTOK], tok-perm
__device__ float g_AO[(size_t)NTOK * D_DIM];   // tf32+perm (written by flash)
// Pre-converted (tf32-rounded, 16-chunk k-permuted) operands
__device__ float g_xt[(size_t)NTOK * D_DIM];
__device__ float g_Wqt[(size_t)D_DIM * D_DIM];
__device__ float g_Wkt[(size_t)KVD * D_DIM];
__device__ float g_Wvt[(size_t)KVD * D_DIM];
__device__ float g_Wot[(size_t)D_DIM * D_DIM];

__device__ __forceinline__ uint32_t f2tf32(float x) {
    uint32_t r;
    asm("cvt.rna.tf32.f32 %0, %1;" : "=r"(r) : "f"(x));
    return r;
}
__device__ __forceinline__ uint32_t smem_u32(const void* p) {
    uint32_t a;
    asm("{ .reg .u64 t; cvta.to.shared.u64 t, %1; cvt.u32.u64 %0, t; }"
        : "=r"(a) : "l"(p));
    return a;
}
__device__ __forceinline__ int perm16(int c) {
    return (c & ~15) | ((c & 3) << 2) | ((c >> 2) & 3);
}

#define CP_ASYNC16(dst, src) \
    asm volatile("cp.async.cg.shared.global [%0], [%1], 16;" :: "r"(dst), "l"(src))
#define CP_COMMIT() asm volatile("cp.async.commit_group;" ::: "memory")
#define CP_WAIT(n)  asm volatile("cp.async.wait_group %0;" :: "n"(n) : "memory")

// mma.sync m16n8k8 tf32
__device__ __forceinline__ void mma_tf32(
    float& c0, float& c1, float& c2, float& c3,
    uint32_t a0, uint32_t a1, uint32_t a2, uint32_t a3,
    uint32_t b0, uint32_t b1)
{
    asm volatile(
        "mma.sync.aligned.m16n8k8.row.col.f32.tf32.tf32.f32 "
        "{%0,%1,%2,%3}, {%4,%5,%6,%7}, {%8,%9}, {%0,%1,%2,%3};"
        : "+f"(c0), "+f"(c1), "+f"(c2), "+f"(c3)
        : "r"(a0), "r"(a1), "r"(a2), "r"(a3), "r"(b0), "r"(b1));
}

// ---------------------------------------------------------------------------
// Segmented convert: fp32 -> tf32(rna) + 16-chunk k-perm, one launch.
// ---------------------------------------------------------------------------
#define N4_X  (NTOK * D_DIM / 4)
#define N4_WQ (D_DIM * D_DIM / 4)
#define N4_WK (KVD * D_DIM / 4)
#define SEG0 (N4_X)
#define SEG1 (SEG0 + N4_WQ)
#define SEG2 (SEG1 + N4_WK)
#define SEG3 (SEG2 + N4_WK)
#define SEG4 (SEG3 + N4_WQ)

__global__ __launch_bounds__(256) void convert_all(
    const float* __restrict__ x,  const float* __restrict__ Wq,
    const float* __restrict__ Wk, const float* __restrict__ Wv,
    const float* __restrict__ Wo)
{
    int i = blockIdx.x * 256 + threadIdx.x;
    if (i >= SEG4) return;
    const float* src;
    float* dst;
    int j;
    if (i < SEG0)      { src = x;  dst = g_xt;  j = i; }
    else if (i < SEG1) { src = Wq; dst = g_Wqt; j = i - SEG0; }
    else if (i < SEG2) { src = Wk; dst = g_Wkt; j = i - SEG1; }
    else if (i < SEG3) { src = Wv; dst = g_Wvt; j = i - SEG2; }
    else               { src = Wo; dst = g_Wot; j = i - SEG3; }
    float4 v = ((const float4*)src)[j];
    int f0 = j << 2;
    int base = f0 & ~15;
    int q = (f0 >> 2) & 3;
    dst[base + 0 + q]  = __uint_as_float(f2tf32(v.x));
    dst[base + 4 + q]  = __uint_as_float(f2tf32(v.y));
    dst[base + 8 + q]  = __uint_as_float(f2tf32(v.z));
    dst[base + 12 + q] = __uint_as_float(f2tf32(v.w));
}

// ---------------------------------------------------------------------------
// Shared GEMM body: C_tile = A[128 rows] @ B[128 cols]^T, K k-slabs, 4-stage
// cp.async. Emits result via epilogue branch (vmode).
// ---------------------------------------------------------------------------
struct GemmJob {
    const float* Ap;     // A + rowBase*K
    const float* Bp;     // B + colBase*K
    const float* bias;   // + colBase applied in epilogue via col index
    float* C;
    int N, K, rowBase, colBase, vmode;
};

__device__ __forceinline__ void gemm_body(const GemmJob& jb, float* gsm)
{
    float* sA = gsm;
    float* sB = gsm + 4 * 2048;
    const uint32_t sAu = smem_u32(sA);
    const uint32_t sBu = smem_u32(sB);

    const int tid = threadIdx.x;
    const int lane = tid & 31, wid = tid >> 5;
    const int wm = wid >> 1, wn = wid & 1;
    const int g = lane >> 2, tg = lane & 3;
    const int lrow = tid >> 2;
    const int lc4 = tid & 3;
    const int K = jb.K;

    float acc[2][8][4];
#pragma unroll
    for (int mt = 0; mt < 2; mt++)
#pragma unroll
        for (int nt = 0; nt < 8; nt++)
#pragma unroll
            for (int r = 0; r < 4; r++) acc[mt][nt][r] = 0.0f;

    const int NT = K >> 4;

    auto issue = [&](int slot, int t) {
#pragma unroll
        for (int p = 0; p < 2; p++) {
            const int row = lrow + p * 64;
            const size_t go = (size_t)row * K + t * 16 + lc4 * 4;
            const uint32_t so = (uint32_t)((slot * 2048 + row * 16 + lc4 * 4) * 4);
            CP_ASYNC16(sAu + so, jb.Ap + go);
            CP_ASYNC16(sBu + so, jb.Bp + go);
        }
    };

#pragma unroll
    for (int s = 0; s < 3; s++) { issue(s, s); CP_COMMIT(); }

    for (int t = 0; t < NT; t++) {
        CP_WAIT(2);
        __syncthreads();
        const int tn = t + 3;
        if (tn < NT) issue(tn & 3, tn);
        CP_COMMIT();

        const float* bA = sA + (t & 3) * 2048;
        const float* bB = sB + (t & 3) * 2048;

        uint4 afr[2][2];
#pragma unroll
        for (int mt = 0; mt < 2; mt++) {
            const int r0 = wm * 32 + mt * 16 + g;
            afr[mt][0] = *(const uint4*)&bA[r0 * 16 + 4 * tg];
            afr[mt][1] = *(const uint4*)&bA[(r0 + 8) * 16 + 4 * tg];
        }
        uint4 bfr[8];
#pragma unroll
        for (int nt = 0; nt < 8; nt++)
            bfr[nt] = *(const uint4*)&bB[(wn * 64 + nt * 8 + g) * 16 + 4 * tg];

#pragma unroll
        for (int mt = 0; mt < 2; mt++)
#pragma unroll
            for (int nt = 0; nt < 8; nt++)
                mma_tf32(acc[mt][nt][0], acc[mt][nt][1], acc[mt][nt][2], acc[mt][nt][3],
                         afr[mt][0].x, afr[mt][1].x, afr[mt][0].y, afr[mt][1].y,
                         bfr[nt].x, bfr[nt].y);
#pragma unroll
        for (int mt = 0; mt < 2; mt++)
#pragma unroll
            for (int nt = 0; nt < 8; nt++)
                mma_tf32(acc[mt][nt][0], acc[mt][nt][1], acc[mt][nt][2], acc[mt][nt][3],
                         afr[mt][0].z, afr[mt][1].z, afr[mt][0].w, afr[mt][1].w,
                         bfr[nt].z, bfr[nt].w);
    }

    if (!jb.vmode) {
#pragma unroll
        for (int mt = 0; mt < 2; mt++) {
            const int row = jb.rowBase + wm * 32 + mt * 16 + g;
#pragma unroll
            for (int nt = 0; nt < 8; nt++) {
                const int col = jb.colBase + wn * 64 + nt * 8 + 2 * tg;
                const float2 bb = *(const float2*)(jb.bias + col);
                float2 o0, o1;
                o0.x = acc[mt][nt][0] + bb.x;
                o0.y = acc[mt][nt][1] + bb.y;
                o1.x = acc[mt][nt][2] + bb.x;
                o1.y = acc[mt][nt][3] + bb.y;
                *(float2*)(jb.C + (size_t)row * jb.N + col) = o0;
                *(float2*)(jb.C + (size_t)(row + 8) * jb.N + col) = o1;
            }
        }
    } else {
#pragma unroll
        for (int mt = 0; mt < 2; mt++) {
            const int r = jb.rowBase + wm * 32 + mt * 16 + g;
            const int rp0 = perm16(r);
            const int rp1 = perm16(r + 8);
#pragma unroll
            for (int nt = 0; nt < 8; nt++) {
                const int col = jb.colBase + wn * 64 + nt * 8 + 2 * tg;
                const float b0 = jb.bias[col], b1 = jb.bias[col + 1];
                jb.C[(size_t)col * NTOK + rp0] =
                    __uint_as_float(f2tf32(acc[mt][nt][0] + b0));
                jb.C[(size_t)(col + 1) * NTOK + rp0] =
                    __uint_as_float(f2tf32(acc[mt][nt][1] + b1));
                jb.C[(size_t)col * NTOK + rp1] =
                    __uint_as_float(f2tf32(acc[mt][nt][2] + b0));
                jb.C[(size_t)(col + 1) * NTOK + rp1] =
                    __uint_as_float(f2tf32(acc[mt][nt][3] + b1));
            }
        }
    }
}

// ---------------------------------------------------------------------------
// Fused Q+K+V projection, one launch, flat 768-block grid.
// blocks [0,512): Q tiles; [512,640): K tiles; [640,768): V tiles (vmode 1).
// ---------------------------------------------------------------------------
__global__ __launch_bounds__(256) void gemm_qkv(
    const float* __restrict__ bq, const float* __restrict__ bk,
    const float* __restrict__ bv)
{
    extern __shared__ __align__(16) float gsm[];
    GemmJob jb;
    jb.K = D_DIM;
    const int blk = blockIdx.x;
    if (blk < 512) {
        jb.rowBase = (blk >> 4) * 128; jb.colBase = (blk & 15) * 128;
        jb.Bp = g_Wqt + (size_t)jb.colBase * D_DIM;
        jb.bias = bq; jb.C = g_Q; jb.N = D_DIM; jb.vmode = 0;
    } else if (blk < 640) {
        const int t = blk - 512;
        jb.rowBase = (t >> 2) * 128; jb.colBase = (t & 3) * 128;
        jb.Bp = g_Wkt + (size_t)jb.colBase * D_DIM;
        jb.bias = bk; jb.C = g_K; jb.N = KVD; jb.vmode = 0;
    } else {
        const int t = blk - 640;
        jb.rowBase = (t >> 2) * 128; jb.colBase = (t & 3) * 128;
        jb.Bp = g_Wvt + (size_t)jb.colBase * D_DIM;
        jb.bias = bv; jb.C = g_Vt; jb.N = KVD; jb.vmode = 1;
    }
    jb.Ap = g_xt + (size_t)jb.rowBase * D_DIM;
    gemm_body(jb, gsm);
}

// ---------------------------------------------------------------------------
// Output projection (generic single GEMM)
// ---------------------------------------------------------------------------
__global__ __launch_bounds__(256) void gemm_out(
    const float* __restrict__ bias, float* __restrict__ C)
{
    extern __shared__ __align__(16) float gsm[];
    GemmJob jb;
    jb.K = D_DIM;
    jb.rowBase = blockIdx.y * 128;
    jb.colBase = blockIdx.x * 128;
    jb.Ap = g_AO + (size_t)jb.rowBase * D_DIM;
    jb.Bp = g_Wot + (size_t)jb.colBase * D_DIM;
    jb.bias = bias; jb.C = C; jb.N = D_DIM; jb.vmode = 0;
    gemm_body(jb, gsm);
}

// ---------------------------------------------------------------------------
// Fused RMSNorm + RoPE; writes tf32-rounded, k-permuted output in place.
// ---------------------------------------------------------------------------
__global__ __launch_bounds__(256) void rms_rope(
    float* __restrict__ T, int nheads, const float* __restrict__ gain,
    float extrascale)
{
    int gw = (blockIdx.x * blockDim.x + threadIdx.x) >> 5;
    int lane = threadIdx.x & 31;
    int token = gw / nheads;
    int h = gw - token * nheads;
    if (token >= NTOK) return;

    float* p = T + (size_t)token * (nheads * HD) + h * HD;
    float a1 = p[lane];
    float b1 = p[lane + 32];
    float a2 = p[lane + 64];
    float b2 = p[lane + 96];

    float ss = a1 * a1 + b1 * b1 + a2 * a2 + b2 * b2;
#pragma unroll
    for (int off = 16; off; off >>= 1)
        ss += __shfl_xor_sync(0xffffffffu, ss, off);

    float g = rsqrtf(ss * (1.0f / 128.0f) + EPS_F);
    if (gain) g *= gain[h];
    g *= extrascale;

    int pos = token & (S_LEN - 1);
    const float c = -0.20762050593046015f;  // -log2(10000)/64
    float invfa = exp2f(c * (float)lane);
    float invfb = exp2f(c * (float)(lane + 32));
    float sa, ca, sb, cb;
    sincosf((float)pos * invfa, &sa, &ca);
    sincosf((float)pos * invfb, &sb, &cb);

    p[perm16(lane)]      = __uint_as_float(f2tf32((a1 * ca + a2 * sa) * g));
    p[perm16(lane + 64)] = __uint_as_float(f2tf32((a2 * ca - a1 * sa) * g));
    p[perm16(lane + 32)] = __uint_as_float(f2tf32((b1 * cb + b2 * sb) * g));
    p[perm16(lane + 96)] = __uint_as_float(f2tf32((b2 * cb - b1 * sb) * g));
}

// ---------------------------------------------------------------------------
// Causal flash attention, tf32 mma + cp.async pipeline, LPT block order.
// ---------------------------------------------------------------------------
#define QROWS 132
#define VROWS 68

__global__ __launch_bounds__(256) void flash_tf32()
{
    extern __shared__ __align__(16) uint32_t usm[];
    uint32_t* Qs = usm;                    // [128][QROWS]
    uint32_t* Ks = Qs + 128 * QROWS;       // [64][QROWS]
    uint32_t* Vt = Ks + 64 * QROWS;        // [128][VROWS]
    uint32_t* Ps = Vt + 128 * VROWS;       // [8][16][VROWS]
    const uint32_t Ksu = smem_u32(Ks);
    const uint32_t Vtu = smem_u32(Vt);

    // LPT: heaviest q-tiles (largest qt) launch first
    const int qt = gridDim.x - 1 - blockIdx.x;
    const int bh = blockIdx.y;
    const int b = bh >> 4, h = bh & 15, kvh = h >> 2;
    const int tid = threadIdx.x;
    const int lane = tid & 31, w = tid >> 5;
    const int g = lane >> 2, tg = lane & 3;

    const float* Qg = g_Q + ((size_t)(b * S_LEN + qt * 128)) * D_DIM + h * HD;
    const float* Kg = g_K + ((size_t)b * S_LEN) * KVD + kvh * HD;
    const float* Vg = g_Vt + (size_t)(kvh * HD) * NTOK + b * S_LEN;

    const int krow = tid >> 5, kc4 = tid & 31;
    const int vd = tid >> 4, vc4 = tid & 15;
    auto issueK = [&](int kt) {
#pragma unroll
        for (int i = 0; i < 8; i++) {
            int row = krow + i * 8;
            CP_ASYNC16(Ksu + (uint32_t)((row * QROWS + kc4 * 4) * 4),
                       Kg + (size_t)(kt * 64 + row) * KVD + kc4 * 4);
        }
    };
    auto issueV = [&](int kt) {
#pragma unroll
        for (int i = 0; i < 8; i++) {
            int d = vd + i * 16;
            CP_ASYNC16(Vtu + (uint32_t)((d * VROWS + vc4 * 4) * 4),
                       Vg + (size_t)d * NTOK + kt * 64 + vc4 * 4);
        }
    };

    const int nkt = 2 * qt + 2;
    issueK(0); CP_COMMIT();
    issueV(0); CP_COMMIT();

#pragma unroll
    for (int i = 0; i < 16; i++) {
        int idx = tid + i * 256;
        int row = idx >> 5, c4 = idx & 31;
        *(uint4*)&Qs[row * QROWS + c4 * 4] =
            *(const uint4*)(Qg + (size_t)row * D_DIM + c4 * 4);
    }

    float o[16][4];
#pragma unroll
    for (int nt = 0; nt < 16; nt++)
#pragma unroll
        for (int r = 0; r < 4; r++) o[nt][r] = 0.0f;
    float m0 = -1e30f, m1 = -1e30f, l0 = 0.0f, l1 = 0.0f;

    uint32_t* Pw = Ps + w * 16 * VROWS;

    for (int kt = 0; kt < nkt; kt++) {
        const int kn = (kt + 1 < nkt) ? kt + 1 : kt;

        CP_WAIT(1);
        __syncthreads();

        float sacc[8][4];
#pragma unroll
        for (int nt = 0; nt < 8; nt++)
#pragma unroll
            for (int r = 0; r < 4; r++) sacc[nt][r] = 0.0f;

#pragma unroll
        for (int ch = 0; ch < 8; ch++) {
            uint4 a0 = *(const uint4*)&Qs[(w * 16 + g) * QROWS + ch * 16 + 4 * tg];
            uint4 a1 = *(const uint4*)&Qs[(w * 16 + g + 8) * QROWS + ch * 16 + 4 * tg];
#pragma unroll
            for (int nt = 0; nt < 8; nt++) {
                uint4 bf = *(const uint4*)&Ks[(nt * 8 + g) * QROWS + ch * 16 + 4 * tg];
                mma_tf32(sacc[nt][0], sacc[nt][1], sacc[nt][2], sacc[nt][3],
                         a0.x, a1.x, a0.y, a1.y, bf.x, bf.y);
                mma_tf32(sacc[nt][0], sacc[nt][1], sacc[nt][2], sacc[nt][3],
                         a0.z, a1.z, a0.w, a1.w, bf.z, bf.w);
            }
        }

        CP_WAIT(0);
        __syncthreads();

        issueK(kn); CP_COMMIT();

        if (kt >= 2 * qt) {
            const int q0 = qt * 128 + w * 16 + g;
            const int q1 = q0 + 8;
#pragma unroll
            for (int nt = 0; nt < 8; nt++) {
                int k0 = kt * 64 + nt * 8 + 2 * tg;
                if (k0 > q0)     sacc[nt][0] = -1e30f;
                if (k0 + 1 > q0) sacc[nt][1] = -1e30f;
                if (k0 > q1)     sacc[nt][2] = -1e30f;
                if (k0 + 1 > q1) sacc[nt][3] = -1e30f;
            }
        }

        float mx0 = -1e30f, mx1 = -1e30f;
#pragma unroll
        for (int nt = 0; nt < 8; nt++) {
            mx0 = fmaxf(mx0, fmaxf(sacc[nt][0], sacc[nt][1]));
            mx1 = fmaxf(mx1, fmaxf(sacc[nt][2], sacc[nt][3]));
        }
        mx0 = fmaxf(mx0, __shfl_xor_sync(0xffffffffu, mx0, 1));
        mx0 = fmaxf(mx0, __shfl_xor_sync(0xffffffffu, mx0, 2));
        mx1 = fmaxf(mx1, __shfl_xor_sync(0xffffffffu, mx1, 1));
        mx1 = fmaxf(mx1, __shfl_xor_sync(0xffffffffu, mx1, 2));
        const float nm0 = fmaxf(m0, mx0), nm1 = fmaxf(m1, mx1);
        const float cr0 = __expf(m0 - nm0), cr1 = __expf(m1 - nm1);
        m0 = nm0; m1 = nm1;

        float s0 = 0.0f, s1 = 0.0f;
#pragma unroll
        for (int nt = 0; nt < 8; nt++) {
#pragma unroll
            for (int jj = 0; jj < 2; jj++) {
                int kk = nt * 8 + 2 * tg + jj;
                int kp = perm16(kk);
                float p0 = __expf(sacc[nt][jj] - nm0);
                s0 += p0;
                Pw[g * VROWS + kp] = f2tf32(p0);
                float p1 = __expf(sacc[nt][2 + jj] - nm1);
                s1 += p1;
                Pw[(g + 8) * VROWS + kp] = f2tf32(p1);
            }
        }
        s0 += __shfl_xor_sync(0xffffffffu, s0, 1);
        s0 += __shfl_xor_sync(0xffffffffu, s0, 2);
        s1 += __shfl_xor_sync(0xffffffffu, s1, 1);
        s1 += __shfl_xor_sync(0xffffffffu, s1, 2);
        l0 = l0 * cr0 + s0;
        l1 = l1 * cr1 + s1;

#pragma unroll
        for (int nt = 0; nt < 16; nt++) {
            o[nt][0] *= cr0; o[nt][1] *= cr0;
            o[nt][2] *= cr1; o[nt][3] *= cr1;
        }
        __syncwarp();

#pragma unroll
        for (int ck = 0; ck < 4; ck++) {
            uint4 p0 = *(const uint4*)&Pw[g * VROWS + ck * 16 + 4 * tg];
            uint4 p1 = *(const uint4*)&Pw[(g + 8) * VROWS + ck * 16 + 4 * tg];
#pragma unroll
            for (int nt = 0; nt < 16; nt++) {
                uint4 bf = *(const uint4*)&Vt[(nt * 8 + g) * VROWS + ck * 16 + 4 * tg];
                mma_tf32(o[nt][0], o[nt][1], o[nt][2], o[nt][3],
                         p0.x, p1.x, p0.y, p1.y, bf.x, bf.y);
                mma_tf32(o[nt][0], o[nt][1], o[nt][2], o[nt][3],
                         p0.z, p1.z, p0.w, p1.w, bf.z, bf.w);
            }
        }

        __syncthreads();
        issueV(kn); CP_COMMIT();
    }

    const float inv0 = 1.0f / l0, inv1 = 1.0f / l1;
    float* Og = g_AO + ((size_t)(b * S_LEN + qt * 128 + w * 16)) * D_DIM + h * HD;
#pragma unroll
    for (int nt = 0; nt < 16; nt++) {
        const int col = nt * 8 + 2 * tg;
        const int pc0 = perm16(col), pc1 = perm16(col + 1);
        Og[(size_t)g * D_DIM + pc0] = __uint_as_float(f2tf32(o[nt][0] * inv0));
        Og[(size_t)g * D_DIM + pc1] = __uint_as_float(f2tf32(o[nt][1] * inv0));
        Og[(size_t)(g + 8) * D_DIM + pc0] = __uint_as_float(f2tf32(o[nt][2] * inv1));
        Og[(size_t)(g + 8) * D_DIM + pc1] = __uint_as_float(f2tf32(o[nt][3] * inv1));
    }
}

// ---------------------------------------------------------------------------
// Launch
// ---------------------------------------------------------------------------
extern "C" void kernel_launch(void* const* d_in, const int* in_sizes, int n_in,
                              void* d_out, int out_size)
{
    const float* x  = (const float*)d_in[0];
    const float* Wq = (const float*)d_in[1];
    const float* bq = (const float*)d_in[2];
    const float* Wk = (const float*)d_in[3];
    const float* bk = (const float*)d_in[4];
    const float* Wv = (const float*)d_in[5];
    const float* bv = (const float*)d_in[6];
    const float* Wo = (const float*)d_in[7];
    const float* bo = (const float*)d_in[8];
    const float* qg = (const float*)d_in[9];
    float* out = (float*)d_out;

    float *Q, *K;
    cudaGetSymbolAddress((void**)&Q, g_Q);
    cudaGetSymbolAddress((void**)&K, g_K);

    const int gemm_smem = 4 * 2048 * 2 * 4;  // 65536
    cudaFuncSetAttribute(gemm_qkv,
                         cudaFuncAttributeMaxDynamicSharedMemorySize, gemm_smem);
    cudaFuncSetAttribute(gemm_out,
                         cudaFuncAttributeMaxDynamicSharedMemorySize, gemm_smem);
    const int flash_smem =
        (128 * QROWS + 64 * QROWS + 128 * VROWS + 8 * 16 * VROWS) * 4;  // 171008
    cudaFuncSetAttribute(flash_tf32,
                         cudaFuncAttributeMaxDynamicSharedMemorySize, flash_smem);

    // 1. Pre-convert all operands
    convert_all<<<(SEG4 + 255) / 256, 256>>>(x, Wq, Wk, Wv, Wo);

    // 2. Fused Q+K+V projections (768 CTAs)
    gemm_qkv<<<768, 256, gemm_smem>>>(bq, bk, bv);

    // 3/4. RMSNorm + RoPE
    rms_rope<<<(NTOK * NH)  / 8, 256>>>(Q, NH,  qg,      0.088388347648318447f);
    rms_rope<<<(NTOK * NKV) / 8, 256>>>(K, NKV, nullptr, 1.0f);

    // 5. Causal flash attention (LPT-ordered)
    flash_tf32<<<dim3(S_LEN / 128, B_SZ * NH), 256, flash_smem>>>();

    // 6. Output projection
    gemm_out<<<dim3(D_DIM / 128, NTOK / 128), 256, gemm_smem>>>(bo, out);
}